// round 6
// baseline (speedup 1.0000x reference)
#include <cuda_runtime.h>
#include <cstdint>

// ---------------------------------------------------------------------------
// HiPPO-LegT full-state scan as parallel GEMMs (chunked C=128, G=16):
//   out[gC+tau] = A^{tau+1} h_g + sum_{j<=tau} K_j f[t-j]
// Round 5: k_main 128x128 tiles (2 CTA/SM), 3-stage cp.async ring, 1 sync/tile;
// k_w moved to tf32 mma. Powers remain fp32 for accuracy.
// ---------------------------------------------------------------------------

#define LSEQ 2048
#define BT   128
#define NST  256
#define CH   128
#define NG   16
#define NPAIR 105
#define MATSZ (NST * NST)

__device__ float    g_T[CH * MATSZ];          // A^{i+1}, fp32
__device__ uint32_t g_Ttf[CH * MATSZ];        // tf32 copies
__device__ float    g_P[(NG - 1) * MATSZ];    // (A^128)^{r+1}
__device__ uint32_t g_Ptf[(NG - 1) * MATSZ];
__device__ float    g_K[CH * NST];            // K_j = A^j B  [j][n]
__device__ uint32_t g_Kttf[NST * CH];         // tf32, transposed [n][j]
__device__ float    g_w[NG * BT * NST];
__device__ uint32_t g_wtf[NG * BT * NST];
__device__ uint32_t g_htf[NG * BT * NST];
__device__ float    g_part[NPAIR * BT * NST];
__device__ int      g_ready[160];

// ============================ helpers ======================================
__device__ __forceinline__ uint32_t smem_u32(const void* p) {
    uint32_t a;
    asm("{ .reg .u64 t; cvta.to.shared.u64 t, %1; cvt.u32.u64 %0, t; }"
        : "=r"(a) : "l"(p));
    return a;
}
__device__ __forceinline__ uint32_t f2tf(float x) {
    uint32_t r;
    asm("cvt.rna.tf32.f32 %0, %1;" : "=r"(r) : "f"(x));
    return r;
}
__device__ __forceinline__ void ldsm4(uint32_t addr, uint32_t& r0, uint32_t& r1,
                                      uint32_t& r2, uint32_t& r3) {
    asm volatile("ldmatrix.sync.aligned.m8n8.x4.shared.b16 {%0,%1,%2,%3}, [%4];"
                 : "=r"(r0), "=r"(r1), "=r"(r2), "=r"(r3) : "r"(addr));
}
__device__ __forceinline__ void mma_tf32(float* c, uint32_t a0, uint32_t a1,
                                         uint32_t a2, uint32_t a3,
                                         uint32_t b0, uint32_t b1) {
    asm volatile(
        "mma.sync.aligned.m16n8k8.row.col.f32.tf32.tf32.f32 "
        "{%0,%1,%2,%3}, {%4,%5,%6,%7}, {%8,%9}, {%0,%1,%2,%3};"
        : "+f"(c[0]), "+f"(c[1]), "+f"(c[2]), "+f"(c[3])
        : "r"(a0), "r"(a1), "r"(a2), "r"(a3), "r"(b0), "r"(b1));
}
#define CP_ASYNC16(dst, src) \
    asm volatile("cp.async.cg.shared.global [%0], [%1], 16;" \
                 :: "r"(dst), "l"(src) : "memory")
#define CP_COMMIT() asm volatile("cp.async.commit_group;" ::: "memory")
#define CP_WAIT1()  asm volatile("cp.async.wait_group 1;" ::: "memory")

__device__ __forceinline__ uint32_t sw_off(int row, int k) {
    return (uint32_t)(row * 128 + ((((k >> 2) ^ (row & 7)) << 4) | ((k & 3) << 2)));
}
__device__ __forceinline__ void wait_ready(int id) {
    if (id == 0) return;
    int v;
    do {
        asm volatile("ld.acquire.gpu.global.b32 %0, [%1];"
                     : "=r"(v) : "l"(g_ready + id));
        if (v < 8) __nanosleep(100);
    } while (v < 8);
}

// ============================ k_init =======================================
__global__ void k_init(const float* __restrict__ A, const float* __restrict__ Bv) {
    int i = blockIdx.x * blockDim.x + threadIdx.x;
    if (i < MATSZ) { g_T[i] = A[i]; g_Ttf[i] = f2tf(A[i]); }
    if (i < NST)   { g_K[i] = Bv[i]; g_Kttf[i * CH] = f2tf(Bv[i]); }
    if (i < 160)   g_ready[i] = 0;
}

// ============================ k_powers (fp32, flag-sync) ===================
__global__ void __launch_bounds__(256) k_powers() {
    const int bid = blockIdx.x;
    const int p = bid >> 3, q = bid & 7;
    const int tid = threadIdx.x;

    int xid, yid, oid;
    const float *X = nullptr, *Y = nullptr;
    float *O = nullptr;
    uint32_t *Otf = nullptr;
    bool is_copy = false;

    if (p < 127) {
        int d = 1 << (31 - __clz(p + 1));
        int z = p + 1 - d;
        xid = z; yid = d - 1; oid = d + z;
        X = g_T + (size_t)xid * MATSZ;
        Y = g_T + (size_t)yid * MATSZ;
        O = g_T + (size_t)oid * MATSZ;
        Otf = g_Ttf + (size_t)oid * MATSZ;
    } else if (p == 127) {
        xid = 127; yid = 127; oid = 128;
        is_copy = true;
    } else {
        int p2 = p - 128, d, z;
        if (p2 < 1)      { d = 1; z = 0; }
        else if (p2 < 3) { d = 2; z = p2 - 1; }
        else if (p2 < 7) { d = 4; z = p2 - 3; }
        else             { d = 8; z = p2 - 7; }
        xid = 128 + z; yid = 128 + d - 1; oid = 128 + d + z;
        X = g_P + (size_t)z * MATSZ;
        Y = g_P + (size_t)(d - 1) * MATSZ;
        O = g_P + (size_t)(d + z) * MATSZ;
        Otf = g_Ptf + (size_t)(d + z) * MATSZ;
    }

    if (tid == 0) {
        wait_ready(xid);
        if (yid != xid) wait_ready(yid);
    }
    __syncthreads();

    if (is_copy) {
        const float* S = g_T + (size_t)127 * MATSZ + q * 8192;
        float* D = g_P + q * 8192;
        uint32_t* Dtf = g_Ptf + q * 8192;
        for (int i = tid; i < 2048; i += 256) {
            float4 v = ((const float4*)S)[i];
            ((float4*)D)[i] = v;
            ((uint4*)Dtf)[i] = make_uint4(f2tf(v.x), f2tf(v.y), f2tf(v.z), f2tf(v.w));
        }
    } else {
        const int r0 = (q >> 2) * 128, c0 = (q & 3) * 64;
        __shared__ float Xs[16][132];
        __shared__ float Ys[16][68];
        const int tx = tid & 15, ty = tid >> 4;
        float acc[8][4];
#pragma unroll
        for (int i = 0; i < 8; i++)
#pragma unroll
            for (int j = 0; j < 4; j++) acc[i][j] = 0.f;

        for (int k0 = 0; k0 < NST; k0 += 16) {
            {
                int rr = tid >> 1, kb = (tid & 1) * 8;
                float4 v0 = *(const float4*)&X[(size_t)(r0 + rr) * NST + k0 + kb];
                float4 v1 = *(const float4*)&X[(size_t)(r0 + rr) * NST + k0 + kb + 4];
                Xs[kb + 0][rr] = v0.x; Xs[kb + 1][rr] = v0.y;
                Xs[kb + 2][rr] = v0.z; Xs[kb + 3][rr] = v0.w;
                Xs[kb + 4][rr] = v1.x; Xs[kb + 5][rr] = v1.y;
                Xs[kb + 6][rr] = v1.z; Xs[kb + 7][rr] = v1.w;
            }
            {
                int kk = tid >> 4, cb = (tid & 15) * 4;
                *(float4*)&Ys[kk][cb] = *(const float4*)&Y[(size_t)(k0 + kk) * NST + c0 + cb];
            }
            __syncthreads();
#pragma unroll
            for (int kk = 0; kk < 16; kk++) {
                float a[8], b[4];
                *(float4*)&a[0] = *(const float4*)&Xs[kk][ty * 8];
                *(float4*)&a[4] = *(const float4*)&Xs[kk][ty * 8 + 4];
                *(float4*)b = *(const float4*)&Ys[kk][tx * 4];
#pragma unroll
                for (int i = 0; i < 8; i++)
#pragma unroll
                    for (int j = 0; j < 4; j++) acc[i][j] += a[i] * b[j];
            }
            __syncthreads();
        }
#pragma unroll
        for (int i = 0; i < 8; i++) {
            size_t idx = (size_t)(r0 + ty * 8 + i) * NST + c0 + tx * 4;
            float4 v = make_float4(acc[i][0], acc[i][1], acc[i][2], acc[i][3]);
            *(float4*)&O[idx] = v;
            *(uint4*)&Otf[idx] = make_uint4(f2tf(v.x), f2tf(v.y), f2tf(v.z), f2tf(v.w));
        }
    }
    __syncthreads();
    if (tid == 0) {
        __threadfence();
        atomicAdd(&g_ready[oid], 1);
    }
}

// ============================ k_kern =======================================
__global__ void k_kern(const float* __restrict__ Bv) {
    int j = blockIdx.x + 1;
    const float* __restrict__ T = g_T + (size_t)(j - 1) * MATSZ;
    __shared__ float Bs[NST];
    int tid = threadIdx.x;
    if (tid < NST) Bs[tid] = Bv[tid];
    __syncthreads();
    int warp = tid >> 5, lane = tid & 31;
    for (int n = warp; n < NST; n += 8) {
        float s = 0.f;
        for (int k = lane; k < NST; k += 32) s += T[(size_t)n * NST + k] * Bs[k];
#pragma unroll
        for (int o = 16; o; o >>= 1) s += __shfl_xor_sync(0xFFFFFFFFu, s, o);
        if (!lane) {
            g_K[j * NST + n] = s;
            g_Kttf[n * CH + j] = f2tf(s);
        }
    }
}

// ============================ k_w (tf32 mma) ===============================
// grid (2, NG): w[g][b][n0..n0+127] = sum_j K_j[n] f[gC+C-1-j][b], K=128.
__global__ void __launch_bounds__(256, 1)
k_w_mma(const float* __restrict__ f) {
    __shared__ uint32_t sA[4096];   // 16KB  [b=128][j=32]
    __shared__ uint32_t sB[4096];   // 16KB  [n=128][j=32]
    const uint32_t As_u = smem_u32(sA);
    const uint32_t Bs_u = smem_u32(sB);

    const int gch = blockIdx.y;
    const int n0 = blockIdx.x * 128;
    const int tid = threadIdx.x;
    const int lane = tid & 31;
    const int wid = tid >> 5;
    const int wm = wid >> 2, wn = wid & 3;

    float acc[4][4][4];
#pragma unroll
    for (int mi = 0; mi < 4; mi++)
#pragma unroll
        for (int ni = 0; ni < 4; ni++)
#pragma unroll
            for (int qq = 0; qq < 4; qq++) acc[mi][ni][qq] = 0.f;

    const int a_row = wm * 64 + (lane & 7) + ((lane >> 3) & 1) * 8;
    const int a_csel = (lane >> 4) & 1;
    const int b_row = wn * 32 + (lane & 7) + ((lane >> 4) << 3);
    const int b_csel = (lane >> 3) & 1;

    for (int itk = 0; itk < 4; ++itk) {
        int j0 = itk * 32;
#pragma unroll
        for (int i = 0; i < 16; i++) {        // A = reversed F
            int e = tid + i * 256;
            int b = e & 127, j = e >> 7;
            int row = gch * CH + CH - 1 - (j0 + j);
            *(uint32_t*)((char*)sA + sw_off(b, j)) = f2tf(f[(size_t)row * BT + b]);
        }
#pragma unroll
        for (int i = 0; i < 4; i++) {         // B = Kt rows n0..n0+127
            int e = tid + i * 256;
            int r = e >> 3, kq = (e & 7) << 2;
            *(uint4*)((char*)sB + sw_off(r, kq)) =
                *(const uint4*)&g_Kttf[(size_t)(n0 + r) * CH + j0 + kq];
        }
        __syncthreads();
#pragma unroll
        for (int kt = 0; kt < 4; kt++) {
            uint32_t a[4][4], b[2][4];
#pragma unroll
            for (int mi = 0; mi < 4; mi++) {
                int r = a_row + mi * 16;
                int kc = kt * 8 + a_csel * 4;
                ldsm4(As_u + (uint32_t)(r * 128) + ((uint32_t)(((kc >> 2) ^ (r & 7)) << 4)),
                      a[mi][0], a[mi][1], a[mi][2], a[mi][3]);
            }
#pragma unroll
            for (int nb = 0; nb < 2; nb++) {
                int r = b_row + nb * 16;
                int kc = kt * 8 + b_csel * 4;
                ldsm4(Bs_u + (uint32_t)(r * 128) + ((uint32_t)(((kc >> 2) ^ (r & 7)) << 4)),
                      b[nb][0], b[nb][1], b[nb][2], b[nb][3]);
            }
#pragma unroll
            for (int mi = 0; mi < 4; mi++)
#pragma unroll
                for (int ni = 0; ni < 4; ni++)
                    mma_tf32(acc[mi][ni], a[mi][0], a[mi][1], a[mi][2], a[mi][3],
                             b[ni >> 1][(ni & 1) * 2], b[ni >> 1][(ni & 1) * 2 + 1]);
        }
        __syncthreads();
    }

    const int er = wm * 64 + (lane >> 2);
    const int ec0 = wn * 32 + (lane & 3) * 2;
#pragma unroll
    for (int mi = 0; mi < 4; mi++) {
        int r0 = er + mi * 16;
#pragma unroll
        for (int ni = 0; ni < 4; ni++) {
            int c = ec0 + ni * 8;
            size_t i0 = ((size_t)gch * BT + r0) * NST + n0 + c;
            size_t i1 = ((size_t)gch * BT + r0 + 8) * NST + n0 + c;
            g_w[i0] = acc[mi][ni][0]; g_w[i0 + 1] = acc[mi][ni][1];
            g_w[i1] = acc[mi][ni][2]; g_w[i1 + 1] = acc[mi][ni][3];
            g_wtf[i0] = f2tf(acc[mi][ni][0]); g_wtf[i0 + 1] = f2tf(acc[mi][ni][1]);
            g_wtf[i1] = f2tf(acc[mi][ni][2]); g_wtf[i1 + 1] = f2tf(acc[mi][ni][3]);
        }
    }
}

// ============================ k_h1 (tf32 mma) ==============================
__global__ void __launch_bounds__(256, 1)
k_h1_mma() {
    extern __shared__ char smem[];
    const uint32_t As_u = smem_u32(smem);
    const uint32_t Bs_u = As_u + 16384;

    int z = blockIdx.x;
    int zr = z, g = 2;
    while (zr >= g - 1) { zr -= g - 1; g++; }
    int m = zr;
    int lag = g - 2 - m;

    const uint32_t* __restrict__ W = g_wtf + (size_t)m * BT * NST;
    const uint32_t* __restrict__ P = g_Ptf + (size_t)lag * MATSZ;
    float* __restrict__ OUT = g_part + (size_t)z * BT * NST;

    const int tid = threadIdx.x;
    const int lane = tid & 31;
    const int wid = tid >> 5;
    const int wm = wid >> 2, wn = wid & 3;

    float acc[4][8][4];
#pragma unroll
    for (int mi = 0; mi < 4; mi++)
#pragma unroll
        for (int ni = 0; ni < 8; ni++)
#pragma unroll
            for (int qq = 0; qq < 4; qq++) acc[mi][ni][qq] = 0.f;

    const int a_row = wm * 64 + (lane & 7) + ((lane >> 3) & 1) * 8;
    const int a_csel = (lane >> 4) & 1;
    const int b_row = wn * 64 + (lane & 7) + ((lane >> 4) << 3);
    const int b_csel = (lane >> 3) & 1;

    for (int it = 0; it < 8; ++it) {
        int k0 = it * 32;
#pragma unroll
        for (int i = 0; i < 4; i++) {
            int e = tid + i * 256;
            int r = e >> 3, kq = (e & 7) << 2;
            *(uint4*)(smem + sw_off(r, kq)) = *(const uint4*)&W[(size_t)r * NST + k0 + kq];
        }
#pragma unroll
        for (int i = 0; i < 8; i++) {
            int e = tid + i * 256;
            int r = e >> 3, kq = (e & 7) << 2;
            *(uint4*)(smem + 16384 + sw_off(r, kq)) = *(const uint4*)&P[(size_t)r * NST + k0 + kq];
        }
        __syncthreads();
#pragma unroll
        for (int kt = 0; kt < 4; kt++) {
            uint32_t a[4][4], b[4][4];
#pragma unroll
            for (int mi = 0; mi < 4; mi++) {
                int r = a_row + mi * 16;
                int kc = kt * 8 + a_csel * 4;
                ldsm4(As_u + (uint32_t)(r * 128) + ((uint32_t)(((kc >> 2) ^ (r & 7)) << 4)),
                      a[mi][0], a[mi][1], a[mi][2], a[mi][3]);
            }
#pragma unroll
            for (int nb = 0; nb < 4; nb++) {
                int r = b_row + nb * 16;
                int kc = kt * 8 + b_csel * 4;
                ldsm4(Bs_u + (uint32_t)(r * 128) + ((uint32_t)(((kc >> 2) ^ (r & 7)) << 4)),
                      b[nb][0], b[nb][1], b[nb][2], b[nb][3]);
            }
#pragma unroll
            for (int mi = 0; mi < 4; mi++)
#pragma unroll
                for (int ni = 0; ni < 8; ni++)
                    mma_tf32(acc[mi][ni], a[mi][0], a[mi][1], a[mi][2], a[mi][3],
                             b[ni >> 1][(ni & 1) * 2], b[ni >> 1][(ni & 1) * 2 + 1]);
        }
        __syncthreads();
    }

    const int er = wm * 64 + (lane >> 2);
    const int ec0 = wn * 64 + (lane & 3) * 2;
#pragma unroll
    for (int mi = 0; mi < 4; mi++) {
        int r0 = er + mi * 16;
#pragma unroll
        for (int ni = 0; ni < 8; ni++) {
            int c = ec0 + ni * 8;
            *(float2*)&OUT[(size_t)r0 * NST + c] =
                make_float2(acc[mi][ni][0], acc[mi][ni][1]);
            *(float2*)&OUT[(size_t)(r0 + 8) * NST + c] =
                make_float2(acc[mi][ni][2], acc[mi][ni][3]);
        }
    }
}

// ============================ k_h2 =========================================
__global__ void k_h2() {
    int i = blockIdx.x * blockDim.x + threadIdx.x;
    if (i >= NG * BT * NST) return;
    int g = i / (BT * NST);
    int r = i % (BT * NST);
    float v = 0.f;
    if (g >= 1) v = g_w[(size_t)(g - 1) * BT * NST + r];
    if (g >= 2) {
        int base = (g - 1) * (g - 2) / 2;
        for (int m = 0; m <= g - 2; m++)
            v += g_part[(size_t)(base + m) * BT * NST + r];
    }
    g_htf[i] = f2tf(v);
}

// ============================ k_main =======================================
// grid (LSEQ, 2): CTA computes out[t][0..127][n0..n0+127].
// 3-stage cp.async ring (32KB/stage), 2 CTAs/SM, one syncthreads per tile.
#define STG_BYTES 32768
#define SMEM_MAIN (3 * STG_BYTES)

__global__ void __launch_bounds__(256, 2)
k_main_mma(const float* __restrict__ f, float* __restrict__ out) {
    extern __shared__ char smem[];
    const uint32_t s0 = smem_u32(smem);

    const int tid = threadIdx.x;
    const int lane = tid & 31;
    const int wid = tid >> 5;
    const int wm = wid >> 2;
    const int wn = wid & 3;

    const int t = blockIdx.x;
    const int n0 = blockIdx.y * 128;
    const int g = t >> 7, tau = t & 127;
    const int p1t = (g > 0) ? 8 : 0;
    const int p2t = (tau >> 5) + 1;
    const int nT = p1t + p2t;

    const uint32_t* __restrict__ Htf = g_htf + (size_t)g * BT * NST;
    const uint32_t* __restrict__ Ttf = g_Ttf + (size_t)tau * MATSZ;

    float acc[4][4][4];
#pragma unroll
    for (int mi = 0; mi < 4; mi++)
#pragma unroll
        for (int ni = 0; ni < 4; ni++)
#pragma unroll
            for (int qq = 0; qq < 4; qq++) acc[mi][ni][qq] = 0.f;

    const int a_row = wm * 64 + (lane & 7) + ((lane >> 3) & 1) * 8;
    const int a_csel = (lane >> 4) & 1;
    const int b_row = wn * 32 + (lane & 7) + ((lane >> 4) << 3);
    const int b_csel = (lane >> 3) & 1;

    auto prefetch = [&](int it) {
        if (it < nT) {
            int s = it - (it / 3) * 3;
            uint32_t Au = s0 + (uint32_t)(s * STG_BYTES);
            uint32_t Bu = Au + 16384;
            if (it < p1t) {
                int k0 = it * 32;
#pragma unroll
                for (int i = 0; i < 4; i++) {
                    int e = tid + i * 256;
                    int r = e >> 3, kq = (e & 7) << 2;
                    CP_ASYNC16(Au + sw_off(r, kq), Htf + (size_t)r * NST + k0 + kq);
                }
#pragma unroll
                for (int i = 0; i < 4; i++) {
                    int e = tid + i * 256;
                    int r = e >> 3, kq = (e & 7) << 2;
                    CP_ASYNC16(Bu + sw_off(r, kq),
                               Ttf + (size_t)(n0 + r) * NST + k0 + kq);
                }
            } else {
                int j0 = (it - p1t) * 32;
#pragma unroll
                for (int i = 0; i < 4; i++) {
                    int e = tid + i * 256;
                    int r = e >> 3, kq = (e & 7) << 2;
                    CP_ASYNC16(Bu + sw_off(r, kq),
                               g_Kttf + (size_t)(n0 + r) * CH + j0 + kq);
                }
#pragma unroll
                for (int i = 0; i < 16; i++) {
                    int e = tid + i * 256;
                    int b = e & 127, j = e >> 7;
                    float v = 0.f;
                    if (j0 + j <= tau) v = f[(size_t)(t - j0 - j) * BT + b];
                    *(uint32_t*)(smem + s * STG_BYTES + sw_off(b, j)) = f2tf(v);
                }
            }
        }
        CP_COMMIT();
    };

    prefetch(0);
    prefetch(1);
    for (int it = 0; it < nT; ++it) {
        CP_WAIT1();
        __syncthreads();

        int s = it - (it / 3) * 3;
        uint32_t Au = s0 + (uint32_t)(s * STG_BYTES);
        uint32_t Bu = Au + 16384;
#pragma unroll
        for (int kt = 0; kt < 4; kt++) {
            uint32_t a[4][4], b[2][4];
#pragma unroll
            for (int mi = 0; mi < 4; mi++) {
                int r = a_row + mi * 16;
                int kc = kt * 8 + a_csel * 4;
                ldsm4(Au + (uint32_t)(r * 128) + ((uint32_t)(((kc >> 2) ^ (r & 7)) << 4)),
                      a[mi][0], a[mi][1], a[mi][2], a[mi][3]);
            }
#pragma unroll
            for (int nb = 0; nb < 2; nb++) {
                int r = b_row + nb * 16;
                int kc = kt * 8 + b_csel * 4;
                ldsm4(Bu + (uint32_t)(r * 128) + ((uint32_t)(((kc >> 2) ^ (r & 7)) << 4)),
                      b[nb][0], b[nb][1], b[nb][2], b[nb][3]);
            }
#pragma unroll
            for (int mi = 0; mi < 4; mi++)
#pragma unroll
                for (int ni = 0; ni < 4; ni++)
                    mma_tf32(acc[mi][ni], a[mi][0], a[mi][1], a[mi][2], a[mi][3],
                             b[ni >> 1][(ni & 1) * 2], b[ni >> 1][(ni & 1) * 2 + 1]);
        }
        prefetch(it + 2);
    }

    float* __restrict__ o = out + (size_t)t * BT * NST + n0;
    const int er = wm * 64 + (lane >> 2);
    const int ec0 = wn * 32 + (lane & 3) * 2;
#pragma unroll
    for (int mi = 0; mi < 4; mi++) {
        int r0 = er + mi * 16;
#pragma unroll
        for (int ni = 0; ni < 4; ni++) {
            int c = ec0 + ni * 8;
            *(float2*)&o[(size_t)r0 * NST + c] =
                make_float2(acc[mi][ni][0], acc[mi][ni][1]);
            *(float2*)&o[(size_t)(r0 + 8) * NST + c] =
                make_float2(acc[mi][ni][2], acc[mi][ni][3]);
        }
    }
}

// ---------------------------------------------------------------------------
extern "C" void kernel_launch(void* const* d_in, const int* in_sizes, int n_in,
                              void* d_out, int out_size) {
    const float* f = nullptr;
    const float* A = nullptr;
    const float* Bv = nullptr;
    for (int i = 0; i < n_in; i++) {
        if (in_sizes[i] == LSEQ * BT) f = (const float*)d_in[i];
        else if (in_sizes[i] == NST * NST) A = (const float*)d_in[i];
        else if (in_sizes[i] == NST) Bv = (const float*)d_in[i];
    }
    float* out = (float*)d_out;

    cudaFuncSetAttribute(k_main_mma, cudaFuncAttributeMaxDynamicSharedMemorySize,
                         SMEM_MAIN);
    cudaFuncSetAttribute(k_h1_mma, cudaFuncAttributeMaxDynamicSharedMemorySize,
                         49152);

    k_init<<<256, 256>>>(A, Bv);
    k_powers<<<142 * 8, 256>>>();
    k_kern<<<CH - 1, 256>>>(Bv);
    k_w_mma<<<dim3(2, NG), 256>>>(f);
    k_h1_mma<<<NPAIR, 256, 49152>>>();
    k_h2<<<(NG * BT * NST + 255) / 256, 256>>>();
    k_main_mma<<<dim3(LSEQ, 2), 256, SMEM_MAIN>>>(f, out);
    (void)out_size;
}

// round 8
// speedup vs baseline: 1.0115x; 1.0115x over previous
#include <cuda_runtime.h>
#include <cstdint>

// ---------------------------------------------------------------------------
// HiPPO-LegT full-state scan as parallel GEMMs (chunked C=128, G=16):
//   out[gC+tau] = A^{tau+1} h_g + sum_{j<=tau} K_j f[t-j]
// Round 7 (= round 6 resubmit after infra failure): k_main designed for
// 2 CTAs/SM (<=128 regs via 64x32 warp tiles), 3-stage cp.async ring,
// grid (2, LSEQ) for same-t L2 pairing.
// ---------------------------------------------------------------------------

#define LSEQ 2048
#define BT   128
#define NST  256
#define CH   128
#define NG   16
#define NPAIR 105
#define MATSZ (NST * NST)

__device__ float    g_T[CH * MATSZ];          // A^{i+1}, fp32
__device__ uint32_t g_Ttf[CH * MATSZ];        // tf32 copies
__device__ float    g_P[(NG - 1) * MATSZ];    // (A^128)^{r+1}
__device__ uint32_t g_Ptf[(NG - 1) * MATSZ];
__device__ float    g_K[CH * NST];            // K_j = A^j B  [j][n]
__device__ uint32_t g_Kttf[NST * CH];         // tf32, transposed [n][j]
__device__ float    g_w[NG * BT * NST];
__device__ uint32_t g_wtf[NG * BT * NST];
__device__ uint32_t g_htf[NG * BT * NST];
__device__ float    g_part[NPAIR * BT * NST];
__device__ int      g_ready[160];

// ============================ helpers ======================================
__device__ __forceinline__ uint32_t smem_u32(const void* p) {
    uint32_t a;
    asm("{ .reg .u64 t; cvta.to.shared.u64 t, %1; cvt.u32.u64 %0, t; }"
        : "=r"(a) : "l"(p));
    return a;
}
__device__ __forceinline__ uint32_t f2tf(float x) {
    uint32_t r;
    asm("cvt.rna.tf32.f32 %0, %1;" : "=r"(r) : "f"(x));
    return r;
}
__device__ __forceinline__ void ldsm4(uint32_t addr, uint32_t& r0, uint32_t& r1,
                                      uint32_t& r2, uint32_t& r3) {
    asm volatile("ldmatrix.sync.aligned.m8n8.x4.shared.b16 {%0,%1,%2,%3}, [%4];"
                 : "=r"(r0), "=r"(r1), "=r"(r2), "=r"(r3) : "r"(addr));
}
__device__ __forceinline__ void mma_tf32(float* c, uint32_t a0, uint32_t a1,
                                         uint32_t a2, uint32_t a3,
                                         uint32_t b0, uint32_t b1) {
    asm volatile(
        "mma.sync.aligned.m16n8k8.row.col.f32.tf32.tf32.f32 "
        "{%0,%1,%2,%3}, {%4,%5,%6,%7}, {%8,%9}, {%0,%1,%2,%3};"
        : "+f"(c[0]), "+f"(c[1]), "+f"(c[2]), "+f"(c[3])
        : "r"(a0), "r"(a1), "r"(a2), "r"(a3), "r"(b0), "r"(b1));
}
#define CP_ASYNC16(dst, src) \
    asm volatile("cp.async.cg.shared.global [%0], [%1], 16;" \
                 :: "r"(dst), "l"(src) : "memory")
#define CP_COMMIT() asm volatile("cp.async.commit_group;" ::: "memory")
#define CP_WAIT1()  asm volatile("cp.async.wait_group 1;" ::: "memory")

__device__ __forceinline__ uint32_t sw_off(int row, int k) {
    return (uint32_t)(row * 128 + ((((k >> 2) ^ (row & 7)) << 4) | ((k & 3) << 2)));
}
__device__ __forceinline__ void wait_ready(int id) {
    if (id == 0) return;
    int v;
    do {
        asm volatile("ld.acquire.gpu.global.b32 %0, [%1];"
                     : "=r"(v) : "l"(g_ready + id));
        if (v < 8) __nanosleep(100);
    } while (v < 8);
}

// ============================ k_init =======================================
__global__ void k_init(const float* __restrict__ A, const float* __restrict__ Bv) {
    int i = blockIdx.x * blockDim.x + threadIdx.x;
    if (i < MATSZ) { g_T[i] = A[i]; g_Ttf[i] = f2tf(A[i]); }
    if (i < NST)   { g_K[i] = Bv[i]; g_Kttf[i * CH] = f2tf(Bv[i]); }
    if (i < 160)   g_ready[i] = 0;
}

// ============================ k_powers (fp32, flag-sync) ===================
__global__ void __launch_bounds__(256) k_powers() {
    const int bid = blockIdx.x;
    const int p = bid >> 3, q = bid & 7;
    const int tid = threadIdx.x;

    int xid, yid, oid;
    const float *X = nullptr, *Y = nullptr;
    float *O = nullptr;
    uint32_t *Otf = nullptr;
    bool is_copy = false;

    if (p < 127) {
        int d = 1 << (31 - __clz(p + 1));
        int z = p + 1 - d;
        xid = z; yid = d - 1; oid = d + z;
        X = g_T + (size_t)xid * MATSZ;
        Y = g_T + (size_t)yid * MATSZ;
        O = g_T + (size_t)oid * MATSZ;
        Otf = g_Ttf + (size_t)oid * MATSZ;
    } else if (p == 127) {
        xid = 127; yid = 127; oid = 128;
        is_copy = true;
    } else {
        int p2 = p - 128, d, z;
        if (p2 < 1)      { d = 1; z = 0; }
        else if (p2 < 3) { d = 2; z = p2 - 1; }
        else if (p2 < 7) { d = 4; z = p2 - 3; }
        else             { d = 8; z = p2 - 7; }
        xid = 128 + z; yid = 128 + d - 1; oid = 128 + d + z;
        X = g_P + (size_t)z * MATSZ;
        Y = g_P + (size_t)(d - 1) * MATSZ;
        O = g_P + (size_t)(d + z) * MATSZ;
        Otf = g_Ptf + (size_t)(d + z) * MATSZ;
    }

    if (tid == 0) {
        wait_ready(xid);
        if (yid != xid) wait_ready(yid);
    }
    __syncthreads();

    if (is_copy) {
        const float* S = g_T + (size_t)127 * MATSZ + q * 8192;
        float* D = g_P + q * 8192;
        uint32_t* Dtf = g_Ptf + q * 8192;
        for (int i = tid; i < 2048; i += 256) {
            float4 v = ((const float4*)S)[i];
            ((float4*)D)[i] = v;
            ((uint4*)Dtf)[i] = make_uint4(f2tf(v.x), f2tf(v.y), f2tf(v.z), f2tf(v.w));
        }
    } else {
        const int r0 = (q >> 2) * 128, c0 = (q & 3) * 64;
        __shared__ float Xs[16][132];
        __shared__ float Ys[16][68];
        const int tx = tid & 15, ty = tid >> 4;
        float acc[8][4];
#pragma unroll
        for (int i = 0; i < 8; i++)
#pragma unroll
            for (int j = 0; j < 4; j++) acc[i][j] = 0.f;

        for (int k0 = 0; k0 < NST; k0 += 16) {
            {
                int rr = tid >> 1, kb = (tid & 1) * 8;
                float4 v0 = *(const float4*)&X[(size_t)(r0 + rr) * NST + k0 + kb];
                float4 v1 = *(const float4*)&X[(size_t)(r0 + rr) * NST + k0 + kb + 4];
                Xs[kb + 0][rr] = v0.x; Xs[kb + 1][rr] = v0.y;
                Xs[kb + 2][rr] = v0.z; Xs[kb + 3][rr] = v0.w;
                Xs[kb + 4][rr] = v1.x; Xs[kb + 5][rr] = v1.y;
                Xs[kb + 6][rr] = v1.z; Xs[kb + 7][rr] = v1.w;
            }
            {
                int kk = tid >> 4, cb = (tid & 15) * 4;
                *(float4*)&Ys[kk][cb] = *(const float4*)&Y[(size_t)(k0 + kk) * NST + c0 + cb];
            }
            __syncthreads();
#pragma unroll
            for (int kk = 0; kk < 16; kk++) {
                float a[8], b[4];
                *(float4*)&a[0] = *(const float4*)&Xs[kk][ty * 8];
                *(float4*)&a[4] = *(const float4*)&Xs[kk][ty * 8 + 4];
                *(float4*)b = *(const float4*)&Ys[kk][tx * 4];
#pragma unroll
                for (int i = 0; i < 8; i++)
#pragma unroll
                    for (int j = 0; j < 4; j++) acc[i][j] += a[i] * b[j];
            }
            __syncthreads();
        }
#pragma unroll
        for (int i = 0; i < 8; i++) {
            size_t idx = (size_t)(r0 + ty * 8 + i) * NST + c0 + tx * 4;
            float4 v = make_float4(acc[i][0], acc[i][1], acc[i][2], acc[i][3]);
            *(float4*)&O[idx] = v;
            *(uint4*)&Otf[idx] = make_uint4(f2tf(v.x), f2tf(v.y), f2tf(v.z), f2tf(v.w));
        }
    }
    __syncthreads();
    if (tid == 0) {
        __threadfence();
        atomicAdd(&g_ready[oid], 1);
    }
}

// ============================ k_kern =======================================
__global__ void k_kern(const float* __restrict__ Bv) {
    int j = blockIdx.x + 1;
    const float* __restrict__ T = g_T + (size_t)(j - 1) * MATSZ;
    __shared__ float Bs[NST];
    int tid = threadIdx.x;
    if (tid < NST) Bs[tid] = Bv[tid];
    __syncthreads();
    int warp = tid >> 5, lane = tid & 31;
    for (int n = warp; n < NST; n += 8) {
        float s = 0.f;
        for (int k = lane; k < NST; k += 32) s += T[(size_t)n * NST + k] * Bs[k];
#pragma unroll
        for (int o = 16; o; o >>= 1) s += __shfl_xor_sync(0xFFFFFFFFu, s, o);
        if (!lane) {
            g_K[j * NST + n] = s;
            g_Kttf[n * CH + j] = f2tf(s);
        }
    }
}

// ============================ k_w (tf32 mma) ===============================
__global__ void __launch_bounds__(256, 1)
k_w_mma(const float* __restrict__ f) {
    __shared__ uint32_t sA[4096];
    __shared__ uint32_t sB[4096];
    const uint32_t As_u = smem_u32(sA);
    const uint32_t Bs_u = smem_u32(sB);

    const int gch = blockIdx.y;
    const int n0 = blockIdx.x * 128;
    const int tid = threadIdx.x;
    const int lane = tid & 31;
    const int wid = tid >> 5;
    const int wm = wid >> 2, wn = wid & 3;

    float acc[4][4][4];
#pragma unroll
    for (int mi = 0; mi < 4; mi++)
#pragma unroll
        for (int ni = 0; ni < 4; ni++)
#pragma unroll
            for (int qq = 0; qq < 4; qq++) acc[mi][ni][qq] = 0.f;

    const int a_row = wm * 64 + (lane & 7) + ((lane >> 3) & 1) * 8;
    const int a_csel = (lane >> 4) & 1;
    const int b_row = wn * 32 + (lane & 7) + ((lane >> 4) << 3);
    const int b_csel = (lane >> 3) & 1;

    for (int itk = 0; itk < 4; ++itk) {
        int j0 = itk * 32;
#pragma unroll
        for (int i = 0; i < 16; i++) {
            int e = tid + i * 256;
            int b = e & 127, j = e >> 7;
            int row = gch * CH + CH - 1 - (j0 + j);
            *(uint32_t*)((char*)sA + sw_off(b, j)) = f2tf(f[(size_t)row * BT + b]);
        }
#pragma unroll
        for (int i = 0; i < 4; i++) {
            int e = tid + i * 256;
            int r = e >> 3, kq = (e & 7) << 2;
            *(uint4*)((char*)sB + sw_off(r, kq)) =
                *(const uint4*)&g_Kttf[(size_t)(n0 + r) * CH + j0 + kq];
        }
        __syncthreads();
#pragma unroll
        for (int kt = 0; kt < 4; kt++) {
            uint32_t a[4][4], b[2][4];
#pragma unroll
            for (int mi = 0; mi < 4; mi++) {
                int r = a_row + mi * 16;
                int kc = kt * 8 + a_csel * 4;
                ldsm4(As_u + (uint32_t)(r * 128) + ((uint32_t)(((kc >> 2) ^ (r & 7)) << 4)),
                      a[mi][0], a[mi][1], a[mi][2], a[mi][3]);
            }
#pragma unroll
            for (int nb = 0; nb < 2; nb++) {
                int r = b_row + nb * 16;
                int kc = kt * 8 + b_csel * 4;
                ldsm4(Bs_u + (uint32_t)(r * 128) + ((uint32_t)(((kc >> 2) ^ (r & 7)) << 4)),
                      b[nb][0], b[nb][1], b[nb][2], b[nb][3]);
            }
#pragma unroll
            for (int mi = 0; mi < 4; mi++)
#pragma unroll
                for (int ni = 0; ni < 4; ni++)
                    mma_tf32(acc[mi][ni], a[mi][0], a[mi][1], a[mi][2], a[mi][3],
                             b[ni >> 1][(ni & 1) * 2], b[ni >> 1][(ni & 1) * 2 + 1]);
        }
        __syncthreads();
    }

    const int er = wm * 64 + (lane >> 2);
    const int ec0 = wn * 32 + (lane & 3) * 2;
#pragma unroll
    for (int mi = 0; mi < 4; mi++) {
        int r0 = er + mi * 16;
#pragma unroll
        for (int ni = 0; ni < 4; ni++) {
            int c = ec0 + ni * 8;
            size_t i0 = ((size_t)gch * BT + r0) * NST + n0 + c;
            size_t i1 = ((size_t)gch * BT + r0 + 8) * NST + n0 + c;
            g_w[i0] = acc[mi][ni][0]; g_w[i0 + 1] = acc[mi][ni][1];
            g_w[i1] = acc[mi][ni][2]; g_w[i1 + 1] = acc[mi][ni][3];
            g_wtf[i0] = f2tf(acc[mi][ni][0]); g_wtf[i0 + 1] = f2tf(acc[mi][ni][1]);
            g_wtf[i1] = f2tf(acc[mi][ni][2]); g_wtf[i1 + 1] = f2tf(acc[mi][ni][3]);
        }
    }
}

// ============================ k_h1 (tf32 mma) ==============================
__global__ void __launch_bounds__(256, 1)
k_h1_mma() {
    extern __shared__ char smem[];
    const uint32_t As_u = smem_u32(smem);
    const uint32_t Bs_u = As_u + 16384;

    int z = blockIdx.x;
    int zr = z, g = 2;
    while (zr >= g - 1) { zr -= g - 1; g++; }
    int m = zr;
    int lag = g - 2 - m;

    const uint32_t* __restrict__ W = g_wtf + (size_t)m * BT * NST;
    const uint32_t* __restrict__ P = g_Ptf + (size_t)lag * MATSZ;
    float* __restrict__ OUT = g_part + (size_t)z * BT * NST;

    const int tid = threadIdx.x;
    const int lane = tid & 31;
    const int wid = tid >> 5;
    const int wm = wid >> 2, wn = wid & 3;

    float acc[4][8][4];
#pragma unroll
    for (int mi = 0; mi < 4; mi++)
#pragma unroll
        for (int ni = 0; ni < 8; ni++)
#pragma unroll
            for (int qq = 0; qq < 4; qq++) acc[mi][ni][qq] = 0.f;

    const int a_row = wm * 64 + (lane & 7) + ((lane >> 3) & 1) * 8;
    const int a_csel = (lane >> 4) & 1;
    const int b_row = wn * 64 + (lane & 7) + ((lane >> 4) << 3);
    const int b_csel = (lane >> 3) & 1;

    for (int it = 0; it < 8; ++it) {
        int k0 = it * 32;
#pragma unroll
        for (int i = 0; i < 4; i++) {
            int e = tid + i * 256;
            int r = e >> 3, kq = (e & 7) << 2;
            *(uint4*)(smem + sw_off(r, kq)) = *(const uint4*)&W[(size_t)r * NST + k0 + kq];
        }
#pragma unroll
        for (int i = 0; i < 8; i++) {
            int e = tid + i * 256;
            int r = e >> 3, kq = (e & 7) << 2;
            *(uint4*)(smem + 16384 + sw_off(r, kq)) = *(const uint4*)&P[(size_t)r * NST + k0 + kq];
        }
        __syncthreads();
#pragma unroll
        for (int kt = 0; kt < 4; kt++) {
            uint32_t a[4][4], b[4][4];
#pragma unroll
            for (int mi = 0; mi < 4; mi++) {
                int r = a_row + mi * 16;
                int kc = kt * 8 + a_csel * 4;
                ldsm4(As_u + (uint32_t)(r * 128) + ((uint32_t)(((kc >> 2) ^ (r & 7)) << 4)),
                      a[mi][0], a[mi][1], a[mi][2], a[mi][3]);
            }
#pragma unroll
            for (int nb = 0; nb < 4; nb++) {
                int r = b_row + nb * 16;
                int kc = kt * 8 + b_csel * 4;
                ldsm4(Bs_u + (uint32_t)(r * 128) + ((uint32_t)(((kc >> 2) ^ (r & 7)) << 4)),
                      b[nb][0], b[nb][1], b[nb][2], b[nb][3]);
            }
#pragma unroll
            for (int mi = 0; mi < 4; mi++)
#pragma unroll
                for (int ni = 0; ni < 8; ni++)
                    mma_tf32(acc[mi][ni], a[mi][0], a[mi][1], a[mi][2], a[mi][3],
                             b[ni >> 1][(ni & 1) * 2], b[ni >> 1][(ni & 1) * 2 + 1]);
        }
        __syncthreads();
    }

    const int er = wm * 64 + (lane >> 2);
    const int ec0 = wn * 64 + (lane & 3) * 2;
#pragma unroll
    for (int mi = 0; mi < 4; mi++) {
        int r0 = er + mi * 16;
#pragma unroll
        for (int ni = 0; ni < 8; ni++) {
            int c = ec0 + ni * 8;
            *(float2*)&OUT[(size_t)r0 * NST + c] =
                make_float2(acc[mi][ni][0], acc[mi][ni][1]);
            *(float2*)&OUT[(size_t)(r0 + 8) * NST + c] =
                make_float2(acc[mi][ni][2], acc[mi][ni][3]);
        }
    }
}

// ============================ k_h2 =========================================
__global__ void k_h2() {
    int i = blockIdx.x * blockDim.x + threadIdx.x;
    if (i >= NG * BT * NST) return;
    int g = i / (BT * NST);
    int r = i % (BT * NST);
    float v = 0.f;
    if (g >= 1) v = g_w[(size_t)(g - 1) * BT * NST + r];
    if (g >= 2) {
        int base = (g - 1) * (g - 2) / 2;
        for (int m = 0; m <= g - 2; m++)
            v += g_part[(size_t)(base + m) * BT * NST + r];
    }
    g_htf[i] = f2tf(v);
}

// ============================ k_main =======================================
// grid (2, LSEQ): CTA (n-half, t). 128x128 tile, 8 warps 2x4, warp tile 64x32
// (acc 64 regs -> <=128 regs -> 2 CTAs/SM). 3-stage cp.async ring, 32KB/stage.
#define STG_BYTES 32768
#define SMEM_MAIN (3 * STG_BYTES)

__global__ void __launch_bounds__(256, 2)
k_main_mma(const float* __restrict__ f, float* __restrict__ out) {
    extern __shared__ char smem[];
    const uint32_t s0 = smem_u32(smem);

    const int tid = threadIdx.x;
    const int lane = tid & 31;
    const int wid = tid >> 5;
    const int wm = wid >> 2;
    const int wn = wid & 3;

    const int t = blockIdx.y;
    const int n0 = blockIdx.x * 128;
    const int g = t >> 7, tau = t & 127;
    const int p1t = (g > 0) ? 8 : 0;
    const int p2t = (tau >> 5) + 1;
    const int nT = p1t + p2t;

    const uint32_t* __restrict__ Htf = g_htf + (size_t)g * BT * NST;
    const uint32_t* __restrict__ Ttf = g_Ttf + (size_t)tau * MATSZ;

    float acc[4][4][4];
#pragma unroll
    for (int mi = 0; mi < 4; mi++)
#pragma unroll
        for (int ni = 0; ni < 4; ni++)
#pragma unroll
            for (int qq = 0; qq < 4; qq++) acc[mi][ni][qq] = 0.f;

    const int a_row = wm * 64 + (lane & 7) + ((lane >> 3) & 1) * 8;
    const int a_csel = (lane >> 4) & 1;
    const int b_row = wn * 32 + (lane & 7) + ((lane >> 4) << 3);
    const int b_csel = (lane >> 3) & 1;

    auto prefetch = [&](int it) {
        if (it < nT) {
            int s = it - (it / 3) * 3;
            uint32_t Au = s0 + (uint32_t)(s * STG_BYTES);
            uint32_t Bu = Au + 16384;
            if (it < p1t) {
                int k0 = it * 32;
#pragma unroll
                for (int i = 0; i < 4; i++) {
                    int e = tid + i * 256;
                    int r = e >> 3, kq = (e & 7) << 2;
                    CP_ASYNC16(Au + sw_off(r, kq), Htf + (size_t)r * NST + k0 + kq);
                }
#pragma unroll
                for (int i = 0; i < 4; i++) {
                    int e = tid + i * 256;
                    int r = e >> 3, kq = (e & 7) << 2;
                    CP_ASYNC16(Bu + sw_off(r, kq),
                               Ttf + (size_t)(n0 + r) * NST + k0 + kq);
                }
            } else {
                int j0 = (it - p1t) * 32;
#pragma unroll
                for (int i = 0; i < 4; i++) {
                    int e = tid + i * 256;
                    int r = e >> 3, kq = (e & 7) << 2;
                    CP_ASYNC16(Bu + sw_off(r, kq),
                               g_Kttf + (size_t)(n0 + r) * CH + j0 + kq);
                }
#pragma unroll
                for (int i = 0; i < 16; i++) {
                    int e = tid + i * 256;
                    int b = e & 127, j = e >> 7;
                    float v = 0.f;
                    if (j0 + j <= tau) v = f[(size_t)(t - j0 - j) * BT + b];
                    *(uint32_t*)(smem + s * STG_BYTES + sw_off(b, j)) = f2tf(v);
                }
            }
        }
        CP_COMMIT();
    };

    prefetch(0);
    prefetch(1);
    for (int it = 0; it < nT; ++it) {
        CP_WAIT1();
        __syncthreads();

        int s = it - (it / 3) * 3;
        uint32_t Au = s0 + (uint32_t)(s * STG_BYTES);
        uint32_t Bu = Au + 16384;
#pragma unroll
        for (int kt = 0; kt < 4; kt++) {
            uint32_t a[4][4], b[2][4];
#pragma unroll
            for (int mi = 0; mi < 4; mi++) {
                int r = a_row + mi * 16;
                int kc = kt * 8 + a_csel * 4;
                ldsm4(Au + (uint32_t)(r * 128) + ((uint32_t)(((kc >> 2) ^ (r & 7)) << 4)),
                      a[mi][0], a[mi][1], a[mi][2], a[mi][3]);
            }
#pragma unroll
            for (int nb = 0; nb < 2; nb++) {
                int r = b_row + nb * 16;
                int kc = kt * 8 + b_csel * 4;
                ldsm4(Bu + (uint32_t)(r * 128) + ((uint32_t)(((kc >> 2) ^ (r & 7)) << 4)),
                      b[nb][0], b[nb][1], b[nb][2], b[nb][3]);
            }
#pragma unroll
            for (int mi = 0; mi < 4; mi++)
#pragma unroll
                for (int ni = 0; ni < 4; ni++)
                    mma_tf32(acc[mi][ni], a[mi][0], a[mi][1], a[mi][2], a[mi][3],
                             b[ni >> 1][(ni & 1) * 2], b[ni >> 1][(ni & 1) * 2 + 1]);
        }
        prefetch(it + 2);
    }

    float* __restrict__ o = out + (size_t)t * BT * NST + n0;
    const int er = wm * 64 + (lane >> 2);
    const int ec0 = wn * 32 + (lane & 3) * 2;
#pragma unroll
    for (int mi = 0; mi < 4; mi++) {
        int r0 = er + mi * 16;
#pragma unroll
        for (int ni = 0; ni < 4; ni++) {
            int c = ec0 + ni * 8;
            *(float2*)&o[(size_t)r0 * NST + c] =
                make_float2(acc[mi][ni][0], acc[mi][ni][1]);
            *(float2*)&o[(size_t)(r0 + 8) * NST + c] =
                make_float2(acc[mi][ni][2], acc[mi][ni][3]);
        }
    }
}

// ---------------------------------------------------------------------------
extern "C" void kernel_launch(void* const* d_in, const int* in_sizes, int n_in,
                              void* d_out, int out_size) {
    const float* f = nullptr;
    const float* A = nullptr;
    const float* Bv = nullptr;
    for (int i = 0; i < n_in; i++) {
        if (in_sizes[i] == LSEQ * BT) f = (const float*)d_in[i];
        else if (in_sizes[i] == NST * NST) A = (const float*)d_in[i];
        else if (in_sizes[i] == NST) Bv = (const float*)d_in[i];
    }
    float* out = (float*)d_out;

    cudaFuncSetAttribute(k_main_mma, cudaFuncAttributeMaxDynamicSharedMemorySize,
                         SMEM_MAIN);
    cudaFuncSetAttribute(k_h1_mma, cudaFuncAttributeMaxDynamicSharedMemorySize,
                         49152);

    k_init<<<256, 256>>>(A, Bv);
    k_powers<<<142 * 8, 256>>>();
    k_kern<<<CH - 1, 256>>>(Bv);
    k_w_mma<<<dim3(2, NG), 256>>>(f);
    k_h1_mma<<<NPAIR, 256, 49152>>>();
    k_h2<<<(NG * BT * NST + 255) / 256, 256>>>();
    k_main_mma<<<dim3(2, LSEQ), 256, SMEM_MAIN>>>(f, out);
    (void)out_size;
}

// round 9
// speedup vs baseline: 1.2927x; 1.2780x over previous
#include <cuda_runtime.h>
#include <cuda_fp16.h>
#include <cstdint>

// ---------------------------------------------------------------------------
// HiPPO-LegT full-state scan as parallel GEMMs (chunked C=128, G=16):
//   out[gC+tau] = A^{tau+1} h_g + sum_{j<=tau} K_j f[t-j]
// Round 8: k_main on fp16 m16n8k16 (same 11-bit mantissa as tf32, 2x rate,
// half the smem bytes/MAC). Prep unchanged (fp32 powers, tf32 h-path).
// ---------------------------------------------------------------------------

#define LSEQ 2048
#define BT   128
#define NST  256
#define CH   128
#define NG   16
#define NPAIR 105
#define MATSZ (NST * NST)

__device__ float    g_T[CH * MATSZ];          // A^{i+1}, fp32
__device__ __half   g_Th[CH * MATSZ];         // fp16 copies (k_main B, phase1)
__device__ float    g_P[(NG - 1) * MATSZ];    // (A^128)^{r+1}
__device__ uint32_t g_Ptf[(NG - 1) * MATSZ];  // tf32 (k_h1)
__device__ float    g_K[CH * NST];            // K_j = A^j B  [j][n]
__device__ uint32_t g_Kttf[NST * CH];         // tf32 transposed (k_w)
__device__ __half   g_Kth[NST * CH];          // fp16 transposed (k_main conv)
__device__ float    g_w[NG * BT * NST];
__device__ uint32_t g_wtf[NG * BT * NST];
__device__ __half   g_hh[NG * BT * NST];      // fp16 h (k_main A, phase1)
__device__ float    g_part[NPAIR * BT * NST];
__device__ int      g_ready[160];

// ============================ helpers ======================================
__device__ __forceinline__ uint32_t smem_u32(const void* p) {
    uint32_t a;
    asm("{ .reg .u64 t; cvta.to.shared.u64 t, %1; cvt.u32.u64 %0, t; }"
        : "=r"(a) : "l"(p));
    return a;
}
__device__ __forceinline__ uint32_t f2tf(float x) {
    uint32_t r;
    asm("cvt.rna.tf32.f32 %0, %1;" : "=r"(r) : "f"(x));
    return r;
}
__device__ __forceinline__ uint32_t f2h2(float lo, float hi) {
    __half2 h = __floats2half2_rn(lo, hi);
    return *(uint32_t*)&h;
}
__device__ __forceinline__ void ldsm4(uint32_t addr, uint32_t& r0, uint32_t& r1,
                                      uint32_t& r2, uint32_t& r3) {
    asm volatile("ldmatrix.sync.aligned.m8n8.x4.shared.b16 {%0,%1,%2,%3}, [%4];"
                 : "=r"(r0), "=r"(r1), "=r"(r2), "=r"(r3) : "r"(addr));
}
__device__ __forceinline__ void mma_tf32(float* c, uint32_t a0, uint32_t a1,
                                         uint32_t a2, uint32_t a3,
                                         uint32_t b0, uint32_t b1) {
    asm volatile(
        "mma.sync.aligned.m16n8k8.row.col.f32.tf32.tf32.f32 "
        "{%0,%1,%2,%3}, {%4,%5,%6,%7}, {%8,%9}, {%0,%1,%2,%3};"
        : "+f"(c[0]), "+f"(c[1]), "+f"(c[2]), "+f"(c[3])
        : "r"(a0), "r"(a1), "r"(a2), "r"(a3), "r"(b0), "r"(b1));
}
__device__ __forceinline__ void mma_f16(float* c, uint32_t a0, uint32_t a1,
                                        uint32_t a2, uint32_t a3,
                                        uint32_t b0, uint32_t b1) {
    asm volatile(
        "mma.sync.aligned.m16n8k16.row.col.f32.f16.f16.f32 "
        "{%0,%1,%2,%3}, {%4,%5,%6,%7}, {%8,%9}, {%0,%1,%2,%3};"
        : "+f"(c[0]), "+f"(c[1]), "+f"(c[2]), "+f"(c[3])
        : "r"(a0), "r"(a1), "r"(a2), "r"(a3), "r"(b0), "r"(b1));
}
#define CP_ASYNC16(dst, src) \
    asm volatile("cp.async.cg.shared.global [%0], [%1], 16;" \
                 :: "r"(dst), "l"(src) : "memory")
#define CP_COMMIT() asm volatile("cp.async.commit_group;" ::: "memory")
#define CP_WAIT1()  asm volatile("cp.async.wait_group 1;" ::: "memory")

// tf32 swizzle (32 k-floats per 128B row)
__device__ __forceinline__ uint32_t sw_off(int row, int k) {
    return (uint32_t)(row * 128 + ((((k >> 2) ^ (row & 7)) << 4) | ((k & 3) << 2)));
}
__device__ __forceinline__ void wait_ready(int id) {
    if (id == 0) return;
    int v;
    do {
        asm volatile("ld.acquire.gpu.global.b32 %0, [%1];"
                     : "=r"(v) : "l"(g_ready + id));
        if (v < 8) __nanosleep(100);
    } while (v < 8);
}

// ============================ k_init =======================================
__global__ void k_init(const float* __restrict__ A, const float* __restrict__ Bv) {
    int i = blockIdx.x * blockDim.x + threadIdx.x;
    if (i < MATSZ) { g_T[i] = A[i]; g_Th[i] = __float2half_rn(A[i]); }
    if (i < NST) {
        g_K[i] = Bv[i];
        g_Kttf[i * CH] = f2tf(Bv[i]);
        g_Kth[i * CH] = __float2half_rn(Bv[i]);
    }
    if (i < 160) g_ready[i] = 0;
}

// ============================ k_powers (fp32, flag-sync) ===================
__global__ void __launch_bounds__(256) k_powers() {
    const int bid = blockIdx.x;
    const int p = bid >> 3, q = bid & 7;
    const int tid = threadIdx.x;

    int xid, yid, oid;
    const float *X = nullptr, *Y = nullptr;
    float *O = nullptr;
    uint32_t *Otf = nullptr;   // tf32 copies (P mats)
    __half *Oh = nullptr;      // fp16 copies (T mats)
    bool is_copy = false;

    if (p < 127) {
        int d = 1 << (31 - __clz(p + 1));
        int z = p + 1 - d;
        xid = z; yid = d - 1; oid = d + z;
        X = g_T + (size_t)xid * MATSZ;
        Y = g_T + (size_t)yid * MATSZ;
        O = g_T + (size_t)oid * MATSZ;
        Oh = g_Th + (size_t)oid * MATSZ;
    } else if (p == 127) {
        xid = 127; yid = 127; oid = 128;
        is_copy = true;
    } else {
        int p2 = p - 128, d, z;
        if (p2 < 1)      { d = 1; z = 0; }
        else if (p2 < 3) { d = 2; z = p2 - 1; }
        else if (p2 < 7) { d = 4; z = p2 - 3; }
        else             { d = 8; z = p2 - 7; }
        xid = 128 + z; yid = 128 + d - 1; oid = 128 + d + z;
        X = g_P + (size_t)z * MATSZ;
        Y = g_P + (size_t)(d - 1) * MATSZ;
        O = g_P + (size_t)(d + z) * MATSZ;
        Otf = g_Ptf + (size_t)(d + z) * MATSZ;
    }

    if (tid == 0) {
        wait_ready(xid);
        if (yid != xid) wait_ready(yid);
    }
    __syncthreads();

    if (is_copy) {
        const float* S = g_T + (size_t)127 * MATSZ + q * 8192;
        float* D = g_P + q * 8192;
        uint32_t* Dtf = g_Ptf + q * 8192;
        for (int i = tid; i < 2048; i += 256) {
            float4 v = ((const float4*)S)[i];
            ((float4*)D)[i] = v;
            ((uint4*)Dtf)[i] = make_uint4(f2tf(v.x), f2tf(v.y), f2tf(v.z), f2tf(v.w));
        }
    } else {
        const int r0 = (q >> 2) * 128, c0 = (q & 3) * 64;
        __shared__ float Xs[16][132];
        __shared__ float Ys[16][68];
        const int tx = tid & 15, ty = tid >> 4;
        float acc[8][4];
#pragma unroll
        for (int i = 0; i < 8; i++)
#pragma unroll
            for (int j = 0; j < 4; j++) acc[i][j] = 0.f;

        for (int k0 = 0; k0 < NST; k0 += 16) {
            {
                int rr = tid >> 1, kb = (tid & 1) * 8;
                float4 v0 = *(const float4*)&X[(size_t)(r0 + rr) * NST + k0 + kb];
                float4 v1 = *(const float4*)&X[(size_t)(r0 + rr) * NST + k0 + kb + 4];
                Xs[kb + 0][rr] = v0.x; Xs[kb + 1][rr] = v0.y;
                Xs[kb + 2][rr] = v0.z; Xs[kb + 3][rr] = v0.w;
                Xs[kb + 4][rr] = v1.x; Xs[kb + 5][rr] = v1.y;
                Xs[kb + 6][rr] = v1.z; Xs[kb + 7][rr] = v1.w;
            }
            {
                int kk = tid >> 4, cb = (tid & 15) * 4;
                *(float4*)&Ys[kk][cb] = *(const float4*)&Y[(size_t)(k0 + kk) * NST + c0 + cb];
            }
            __syncthreads();
#pragma unroll
            for (int kk = 0; kk < 16; kk++) {
                float a[8], b[4];
                *(float4*)&a[0] = *(const float4*)&Xs[kk][ty * 8];
                *(float4*)&a[4] = *(const float4*)&Xs[kk][ty * 8 + 4];
                *(float4*)b = *(const float4*)&Ys[kk][tx * 4];
#pragma unroll
                for (int i = 0; i < 8; i++)
#pragma unroll
                    for (int j = 0; j < 4; j++) acc[i][j] += a[i] * b[j];
            }
            __syncthreads();
        }
#pragma unroll
        for (int i = 0; i < 8; i++) {
            size_t idx = (size_t)(r0 + ty * 8 + i) * NST + c0 + tx * 4;
            float4 v = make_float4(acc[i][0], acc[i][1], acc[i][2], acc[i][3]);
            *(float4*)&O[idx] = v;
            if (Oh) {
                uint2 hv = make_uint2(f2h2(v.x, v.y), f2h2(v.z, v.w));
                *(uint2*)&Oh[idx] = hv;
            } else {
                *(uint4*)&Otf[idx] =
                    make_uint4(f2tf(v.x), f2tf(v.y), f2tf(v.z), f2tf(v.w));
            }
        }
    }
    __syncthreads();
    if (tid == 0) {
        __threadfence();
        atomicAdd(&g_ready[oid], 1);
    }
}

// ============================ k_kern =======================================
__global__ void k_kern(const float* __restrict__ Bv) {
    int j = blockIdx.x + 1;
    const float* __restrict__ T = g_T + (size_t)(j - 1) * MATSZ;
    __shared__ float Bs[NST];
    int tid = threadIdx.x;
    if (tid < NST) Bs[tid] = Bv[tid];
    __syncthreads();
    int warp = tid >> 5, lane = tid & 31;
    for (int n = warp; n < NST; n += 8) {
        float s = 0.f;
        for (int k = lane; k < NST; k += 32) s += T[(size_t)n * NST + k] * Bs[k];
#pragma unroll
        for (int o = 16; o; o >>= 1) s += __shfl_xor_sync(0xFFFFFFFFu, s, o);
        if (!lane) {
            g_K[j * NST + n] = s;
            g_Kttf[n * CH + j] = f2tf(s);
            g_Kth[n * CH + j] = __float2half_rn(s);
        }
    }
}

// ============================ k_w (tf32 mma) ===============================
__global__ void __launch_bounds__(256, 1)
k_w_mma(const float* __restrict__ f) {
    __shared__ uint32_t sA[4096];
    __shared__ uint32_t sB[4096];
    const uint32_t As_u = smem_u32(sA);
    const uint32_t Bs_u = smem_u32(sB);

    const int gch = blockIdx.y;
    const int n0 = blockIdx.x * 128;
    const int tid = threadIdx.x;
    const int lane = tid & 31;
    const int wid = tid >> 5;
    const int wm = wid >> 2, wn = wid & 3;

    float acc[4][4][4];
#pragma unroll
    for (int mi = 0; mi < 4; mi++)
#pragma unroll
        for (int ni = 0; ni < 4; ni++)
#pragma unroll
            for (int qq = 0; qq < 4; qq++) acc[mi][ni][qq] = 0.f;

    const int a_row = wm * 64 + (lane & 7) + ((lane >> 3) & 1) * 8;
    const int a_csel = (lane >> 4) & 1;
    const int b_row = wn * 32 + (lane & 7) + ((lane >> 4) << 3);
    const int b_csel = (lane >> 3) & 1;

    for (int itk = 0; itk < 4; ++itk) {
        int j0 = itk * 32;
#pragma unroll
        for (int i = 0; i < 16; i++) {
            int e = tid + i * 256;
            int b = e & 127, j = e >> 7;
            int row = gch * CH + CH - 1 - (j0 + j);
            *(uint32_t*)((char*)sA + sw_off(b, j)) = f2tf(f[(size_t)row * BT + b]);
        }
#pragma unroll
        for (int i = 0; i < 4; i++) {
            int e = tid + i * 256;
            int r = e >> 3, kq = (e & 7) << 2;
            *(uint4*)((char*)sB + sw_off(r, kq)) =
                *(const uint4*)&g_Kttf[(size_t)(n0 + r) * CH + j0 + kq];
        }
        __syncthreads();
#pragma unroll
        for (int kt = 0; kt < 4; kt++) {
            uint32_t a[4][4], b[2][4];
#pragma unroll
            for (int mi = 0; mi < 4; mi++) {
                int r = a_row + mi * 16;
                int kc = kt * 8 + a_csel * 4;
                ldsm4(As_u + (uint32_t)(r * 128) + ((uint32_t)(((kc >> 2) ^ (r & 7)) << 4)),
                      a[mi][0], a[mi][1], a[mi][2], a[mi][3]);
            }
#pragma unroll
            for (int nb = 0; nb < 2; nb++) {
                int r = b_row + nb * 16;
                int kc = kt * 8 + b_csel * 4;
                ldsm4(Bs_u + (uint32_t)(r * 128) + ((uint32_t)(((kc >> 2) ^ (r & 7)) << 4)),
                      b[nb][0], b[nb][1], b[nb][2], b[nb][3]);
            }
#pragma unroll
            for (int mi = 0; mi < 4; mi++)
#pragma unroll
                for (int ni = 0; ni < 4; ni++)
                    mma_tf32(acc[mi][ni], a[mi][0], a[mi][1], a[mi][2], a[mi][3],
                             b[ni >> 1][(ni & 1) * 2], b[ni >> 1][(ni & 1) * 2 + 1]);
        }
        __syncthreads();
    }

    const int er = wm * 64 + (lane >> 2);
    const int ec0 = wn * 32 + (lane & 3) * 2;
#pragma unroll
    for (int mi = 0; mi < 4; mi++) {
        int r0 = er + mi * 16;
#pragma unroll
        for (int ni = 0; ni < 4; ni++) {
            int c = ec0 + ni * 8;
            size_t i0 = ((size_t)gch * BT + r0) * NST + n0 + c;
            size_t i1 = ((size_t)gch * BT + r0 + 8) * NST + n0 + c;
            g_w[i0] = acc[mi][ni][0]; g_w[i0 + 1] = acc[mi][ni][1];
            g_w[i1] = acc[mi][ni][2]; g_w[i1 + 1] = acc[mi][ni][3];
            g_wtf[i0] = f2tf(acc[mi][ni][0]); g_wtf[i0 + 1] = f2tf(acc[mi][ni][1]);
            g_wtf[i1] = f2tf(acc[mi][ni][2]); g_wtf[i1 + 1] = f2tf(acc[mi][ni][3]);
        }
    }
}

// ============================ k_h1 (tf32 mma) ==============================
__global__ void __launch_bounds__(256, 1)
k_h1_mma() {
    extern __shared__ char smem[];
    const uint32_t As_u = smem_u32(smem);
    const uint32_t Bs_u = As_u + 16384;

    int z = blockIdx.x;
    int zr = z, g = 2;
    while (zr >= g - 1) { zr -= g - 1; g++; }
    int m = zr;
    int lag = g - 2 - m;

    const uint32_t* __restrict__ W = g_wtf + (size_t)m * BT * NST;
    const uint32_t* __restrict__ P = g_Ptf + (size_t)lag * MATSZ;
    float* __restrict__ OUT = g_part + (size_t)z * BT * NST;

    const int tid = threadIdx.x;
    const int lane = tid & 31;
    const int wid = tid >> 5;
    const int wm = wid >> 2, wn = wid & 3;

    float acc[4][8][4];
#pragma unroll
    for (int mi = 0; mi < 4; mi++)
#pragma unroll
        for (int ni = 0; ni < 8; ni++)
#pragma unroll
            for (int qq = 0; qq < 4; qq++) acc[mi][ni][qq] = 0.f;

    const int a_row = wm * 64 + (lane & 7) + ((lane >> 3) & 1) * 8;
    const int a_csel = (lane >> 4) & 1;
    const int b_row = wn * 64 + (lane & 7) + ((lane >> 4) << 3);
    const int b_csel = (lane >> 3) & 1;

    for (int it = 0; it < 8; ++it) {
        int k0 = it * 32;
#pragma unroll
        for (int i = 0; i < 4; i++) {
            int e = tid + i * 256;
            int r = e >> 3, kq = (e & 7) << 2;
            *(uint4*)(smem + sw_off(r, kq)) = *(const uint4*)&W[(size_t)r * NST + k0 + kq];
        }
#pragma unroll
        for (int i = 0; i < 8; i++) {
            int e = tid + i * 256;
            int r = e >> 3, kq = (e & 7) << 2;
            *(uint4*)(smem + 16384 + sw_off(r, kq)) = *(const uint4*)&P[(size_t)r * NST + k0 + kq];
        }
        __syncthreads();
#pragma unroll
        for (int kt = 0; kt < 4; kt++) {
            uint32_t a[4][4], b[4][4];
#pragma unroll
            for (int mi = 0; mi < 4; mi++) {
                int r = a_row + mi * 16;
                int kc = kt * 8 + a_csel * 4;
                ldsm4(As_u + (uint32_t)(r * 128) + ((uint32_t)(((kc >> 2) ^ (r & 7)) << 4)),
                      a[mi][0], a[mi][1], a[mi][2], a[mi][3]);
            }
#pragma unroll
            for (int nb = 0; nb < 4; nb++) {
                int r = b_row + nb * 16;
                int kc = kt * 8 + b_csel * 4;
                ldsm4(Bs_u + (uint32_t)(r * 128) + ((uint32_t)(((kc >> 2) ^ (r & 7)) << 4)),
                      b[nb][0], b[nb][1], b[nb][2], b[nb][3]);
            }
#pragma unroll
            for (int mi = 0; mi < 4; mi++)
#pragma unroll
                for (int ni = 0; ni < 8; ni++)
                    mma_tf32(acc[mi][ni], a[mi][0], a[mi][1], a[mi][2], a[mi][3],
                             b[ni >> 1][(ni & 1) * 2], b[ni >> 1][(ni & 1) * 2 + 1]);
        }
        __syncthreads();
    }

    const int er = wm * 64 + (lane >> 2);
    const int ec0 = wn * 64 + (lane & 3) * 2;
#pragma unroll
    for (int mi = 0; mi < 4; mi++) {
        int r0 = er + mi * 16;
#pragma unroll
        for (int ni = 0; ni < 8; ni++) {
            int c = ec0 + ni * 8;
            *(float2*)&OUT[(size_t)r0 * NST + c] =
                make_float2(acc[mi][ni][0], acc[mi][ni][1]);
            *(float2*)&OUT[(size_t)(r0 + 8) * NST + c] =
                make_float2(acc[mi][ni][2], acc[mi][ni][3]);
        }
    }
}

// ============================ k_h2 =========================================
__global__ void k_h2() {
    int i = blockIdx.x * blockDim.x + threadIdx.x;
    if (i >= NG * BT * NST) return;
    int g = i / (BT * NST);
    int r = i % (BT * NST);
    float v = 0.f;
    if (g >= 1) v = g_w[(size_t)(g - 1) * BT * NST + r];
    if (g >= 2) {
        int base = (g - 1) * (g - 2) / 2;
        for (int m = 0; m <= g - 2; m++)
            v += g_part[(size_t)(base + m) * BT * NST + r];
    }
    g_hh[i] = __float2half_rn(v);
}

// ============================ k_main (fp16) ================================
// One CTA per t. D[128b x 256n] = H @ T^T + F @ Kt^T in fp16 (fp32 accum).
// k64 tiles: A 128x64 halves (16KB), B 256x64 halves (32KB) -> 48KB/stage,
// 3-stage cp.async ring (144KB). 8 warps 2x4, warp tile 64x64, m16n8k16.
#define STG_BYTES 49152
#define SMEM_MAIN (3 * STG_BYTES)

// fp16 swizzle: 64 halves per 128B row; khalf -> chunk (khalf>>3)
__device__ __forceinline__ uint32_t sw_h(int row, int chunk) {
    return (uint32_t)(row * 128 + ((chunk ^ (row & 7)) << 4));
}

__global__ void __launch_bounds__(256, 1)
k_main_mma(const float* __restrict__ f, float* __restrict__ out) {
    extern __shared__ char smem[];
    const uint32_t s0 = smem_u32(smem);

    const int tid = threadIdx.x;
    const int lane = tid & 31;
    const int wid = tid >> 5;
    const int wm = wid >> 2;    // 0..1
    const int wn = wid & 3;     // 0..3

    const int t = blockIdx.x;
    const int g = t >> 7, tau = t & 127;
    const int p1t = (g > 0) ? 4 : 0;       // K=256 in k64 tiles
    const int p2t = (tau >> 6) + 1;        // 1..2 conv tiles
    const int nT = p1t + p2t;

    const __half* __restrict__ Hh = g_hh + (size_t)g * BT * NST;
    const __half* __restrict__ Th = g_Th + (size_t)tau * MATSZ;

    float acc[4][8][4];
#pragma unroll
    for (int mi = 0; mi < 4; mi++)
#pragma unroll
        for (int ni = 0; ni < 8; ni++)
#pragma unroll
            for (int qq = 0; qq < 4; qq++) acc[mi][ni][qq] = 0.f;

    // fp16 ldmatrix fixed indices
    const int a_r16 = lane & 15;                    // + wm*64 + mi*16
    const int a_kc = (lane >> 4) & 1;               // k8 half select
    const int b_rb = (lane & 7) + ((lane >> 4) & 1) * 8;  // + wn*64 + nbp*16
    const int b_kc = (lane >> 3) & 1;

    auto prefetch = [&](int it) {
        if (it < nT) {
            int s = it - (it / 3) * 3;
            uint32_t Au = s0 + (uint32_t)(s * STG_BYTES);
            uint32_t Bu = Au + 16384;
            if (it < p1t) {
                int k0 = it * 64;
#pragma unroll
                for (int i = 0; i < 4; i++) {       // A = H : 128 rows x 8 chunks
                    int e = tid + i * 256;
                    int r = e >> 3, c = e & 7;
                    CP_ASYNC16(Au + sw_h(r, c), Hh + (size_t)r * NST + k0 + c * 8);
                }
#pragma unroll
                for (int i = 0; i < 8; i++) {       // B = T : 256 rows x 8 chunks
                    int e = tid + i * 256;
                    int r = e >> 3, c = e & 7;
                    CP_ASYNC16(Bu + sw_h(r, c), Th + (size_t)r * NST + k0 + c * 8);
                }
            } else {
                int j0 = (it - p1t) * 64;
#pragma unroll
                for (int i = 0; i < 8; i++) {       // B = Kt
                    int e = tid + i * 256;
                    int r = e >> 3, c = e & 7;
                    CP_ASYNC16(Bu + sw_h(r, c), g_Kth + (size_t)r * CH + j0 + c * 8);
                }
#pragma unroll
                for (int i = 0; i < 4; i++) {       // A = F transposed+masked
                    int e = tid + i * 256;
                    int b = e & 127, jg = e >> 7;   // jg: chunk 0..7
                    uint32_t w[4];
#pragma unroll
                    for (int p2 = 0; p2 < 4; p2++) {
                        int ja = j0 + jg * 8 + p2 * 2;
                        float v0 = (ja     <= tau) ? f[(size_t)(t - ja) * BT + b] : 0.f;
                        float v1 = (ja + 1 <= tau) ? f[(size_t)(t - ja - 1) * BT + b] : 0.f;
                        w[p2] = f2h2(v0, v1);
                    }
                    *(uint4*)(smem + s * STG_BYTES + sw_h(b, jg)) =
                        make_uint4(w[0], w[1], w[2], w[3]);
                }
            }
        }
        CP_COMMIT();
    };

    prefetch(0);
    prefetch(1);
    for (int it = 0; it < nT; ++it) {
        CP_WAIT1();
        __syncthreads();

        int s = it - (it / 3) * 3;
        uint32_t Au = s0 + (uint32_t)(s * STG_BYTES);
        uint32_t Bu = Au + 16384;
#pragma unroll
        for (int kt = 0; kt < 4; kt++) {            // 4 x k16 per k64 tile
            uint32_t a[4][4], b[4][4];
#pragma unroll
            for (int mi = 0; mi < 4; mi++) {
                int r = wm * 64 + mi * 16 + a_r16;
                int c = kt * 2 + a_kc;
                ldsm4(Au + sw_h(r, c), a[mi][0], a[mi][1], a[mi][2], a[mi][3]);
            }
#pragma unroll
            for (int nbp = 0; nbp < 4; nbp++) {
                int r = wn * 64 + nbp * 16 + b_rb;
                int c = kt * 2 + b_kc;
                ldsm4(Bu + sw_h(r, c), b[nbp][0], b[nbp][1], b[nbp][2], b[nbp][3]);
            }
#pragma unroll
            for (int mi = 0; mi < 4; mi++)
#pragma unroll
                for (int n8 = 0; n8 < 8; n8++)
                    mma_f16(acc[mi][n8], a[mi][0], a[mi][1], a[mi][2], a[mi][3],
                            b[n8 >> 1][(n8 & 1) * 2], b[n8 >> 1][(n8 & 1) * 2 + 1]);
        }
        prefetch(it + 2);
    }

    float* __restrict__ o = out + (size_t)t * BT * NST;
    const int er = wm * 64 + (lane >> 2);
    const int ec0 = wn * 64 + (lane & 3) * 2;
#pragma unroll
    for (int mi = 0; mi < 4; mi++) {
        int r0 = er + mi * 16;
#pragma unroll
        for (int n8 = 0; n8 < 8; n8++) {
            int c = ec0 + n8 * 8;
            *(float2*)&o[(size_t)r0 * NST + c] =
                make_float2(acc[mi][n8][0], acc[mi][n8][1]);
            *(float2*)&o[(size_t)(r0 + 8) * NST + c] =
                make_float2(acc[mi][n8][2], acc[mi][n8][3]);
        }
    }
}

// ---------------------------------------------------------------------------
extern "C" void kernel_launch(void* const* d_in, const int* in_sizes, int n_in,
                              void* d_out, int out_size) {
    const float* f = nullptr;
    const float* A = nullptr;
    const float* Bv = nullptr;
    for (int i = 0; i < n_in; i++) {
        if (in_sizes[i] == LSEQ * BT) f = (const float*)d_in[i];
        else if (in_sizes[i] == NST * NST) A = (const float*)d_in[i];
        else if (in_sizes[i] == NST) Bv = (const float*)d_in[i];
    }
    float* out = (float*)d_out;

    cudaFuncSetAttribute(k_main_mma, cudaFuncAttributeMaxDynamicSharedMemorySize,
                         SMEM_MAIN);
    cudaFuncSetAttribute(k_h1_mma, cudaFuncAttributeMaxDynamicSharedMemorySize,
                         49152);

    k_init<<<256, 256>>>(A, Bv);
    k_powers<<<142 * 8, 256>>>();
    k_kern<<<CH - 1, 256>>>(Bv);
    k_w_mma<<<dim3(2, NG), 256>>>(f);
    k_h1_mma<<<NPAIR, 256, 49152>>>();
    k_h2<<<(NG * BT * NST + 255) / 256, 256>>>();
    k_main_mma<<<LSEQ, 256, SMEM_MAIN>>>(f, out);
    (void)out_size;
}

// round 11
// speedup vs baseline: 1.4204x; 1.0988x over previous
#include <cuda_runtime.h>
#include <cuda_fp16.h>
#include <cstdint>

// ---------------------------------------------------------------------------
// HiPPO-LegT full-state scan as parallel GEMMs.
// Round 10 (= round 9 resubmit after infra failure): subchunk-32 restructure.
// out[t] = A^{u+1} H_S + sum_{j<=u} K_j f[t-j], u = t mod 32, S = t/32.
// Powers needed only A^1..A^32, A^64, A^96, (A^128)^r  -> 4x fewer fp32 FLOPs.
// ---------------------------------------------------------------------------

#define LSEQ 2048
#define BT   128
#define NST  256
#define CH   128
#define NG   16
#define NSUB 64          // LSEQ / 32
#define NPAIR 105
#define MATSZ (NST * NST)

// matrix ids: 0..31 = T[i] = A^{i+1}; 32 = A^64; 33 = A^96; 34+r = P[r] = (A^128)^{r+1}
__device__ float    g_T[34 * MATSZ];          // fp32 T-side mats
__device__ uint32_t g_Ttf[34 * MATSZ];        // tf32 copies
__device__ __half   g_Th[32 * MATSZ];         // fp16 copies (k_main phase1 B)
__device__ float    g_P[15 * MATSZ];
__device__ uint32_t g_Ptf[15 * MATSZ];
__device__ float    g_K[32 * NST];            // K_j = A^j B, j<32
__device__ uint32_t g_Kttf[NST * CH];         // tf32 [n][j], j<32 valid, rest 0
__device__ __half   g_Kth[NST * CH];          // fp16 [n][j], j<32 valid, rest 0
__device__ float    g_w2[NSUB * BT * NST];    // subchunk injections
__device__ uint32_t g_w2tf[NSUB * BT * NST];
__device__ float    g_w[NG * BT * NST];       // chunk injections
__device__ uint32_t g_wtf[NG * BT * NST];
__device__ float    g_part[NPAIR * BT * NST];
__device__ uint32_t g_h2tf[NSUB * BT * NST];  // subchunk boundary states (tf32)
__device__ __half   g_hh[NSUB * BT * NST];    // fp16 (k_main phase1 A)
__device__ int      g_ready[64];

// ============================ helpers ======================================
__device__ __forceinline__ uint32_t smem_u32(const void* p) {
    uint32_t a;
    asm("{ .reg .u64 t; cvta.to.shared.u64 t, %1; cvt.u32.u64 %0, t; }"
        : "=r"(a) : "l"(p));
    return a;
}
__device__ __forceinline__ uint32_t f2tf(float x) {
    uint32_t r;
    asm("cvt.rna.tf32.f32 %0, %1;" : "=r"(r) : "f"(x));
    return r;
}
__device__ __forceinline__ uint32_t f2h2(float lo, float hi) {
    __half2 h = __floats2half2_rn(lo, hi);
    return *(uint32_t*)&h;
}
__device__ __forceinline__ void ldsm4(uint32_t addr, uint32_t& r0, uint32_t& r1,
                                      uint32_t& r2, uint32_t& r3) {
    asm volatile("ldmatrix.sync.aligned.m8n8.x4.shared.b16 {%0,%1,%2,%3}, [%4];"
                 : "=r"(r0), "=r"(r1), "=r"(r2), "=r"(r3) : "r"(addr));
}
__device__ __forceinline__ void mma_tf32(float* c, uint32_t a0, uint32_t a1,
                                         uint32_t a2, uint32_t a3,
                                         uint32_t b0, uint32_t b1) {
    asm volatile(
        "mma.sync.aligned.m16n8k8.row.col.f32.tf32.tf32.f32 "
        "{%0,%1,%2,%3}, {%4,%5,%6,%7}, {%8,%9}, {%0,%1,%2,%3};"
        : "+f"(c[0]), "+f"(c[1]), "+f"(c[2]), "+f"(c[3])
        : "r"(a0), "r"(a1), "r"(a2), "r"(a3), "r"(b0), "r"(b1));
}
__device__ __forceinline__ void mma_f16(float* c, uint32_t a0, uint32_t a1,
                                        uint32_t a2, uint32_t a3,
                                        uint32_t b0, uint32_t b1) {
    asm volatile(
        "mma.sync.aligned.m16n8k16.row.col.f32.f16.f16.f32 "
        "{%0,%1,%2,%3}, {%4,%5,%6,%7}, {%8,%9}, {%0,%1,%2,%3};"
        : "+f"(c[0]), "+f"(c[1]), "+f"(c[2]), "+f"(c[3])
        : "r"(a0), "r"(a1), "r"(a2), "r"(a3), "r"(b0), "r"(b1));
}
#define CP_ASYNC16(dst, src) \
    asm volatile("cp.async.cg.shared.global [%0], [%1], 16;" \
                 :: "r"(dst), "l"(src) : "memory")
#define CP_COMMIT() asm volatile("cp.async.commit_group;" ::: "memory")
#define CP_WAIT1()  asm volatile("cp.async.wait_group 1;" ::: "memory")

// tf32 swizzle: 32 floats (128B) per row
__device__ __forceinline__ uint32_t sw_off(int row, int k) {
    return (uint32_t)(row * 128 + ((((k >> 2) ^ (row & 7)) << 4) | ((k & 3) << 2)));
}
__device__ __forceinline__ void wait_ready(int id) {
    if (id == 0) return;
    int v;
    do {
        asm volatile("ld.acquire.gpu.global.b32 %0, [%1];"
                     : "=r"(v) : "l"(g_ready + id));
        if (v < 32) __nanosleep(100);
    } while (v < 32);
}
__device__ __forceinline__ const float* matp(int id) {
    return (id < 34) ? g_T + (size_t)id * MATSZ : g_P + (size_t)(id - 34) * MATSZ;
}

// ============================ k_init =======================================
__global__ void k_init(const float* __restrict__ A, const float* __restrict__ Bv) {
    int i = blockIdx.x * blockDim.x + threadIdx.x;
    if (i < MATSZ) {
        g_T[i] = A[i];
        g_Ttf[i] = f2tf(A[i]);
        g_Th[i] = __float2half_rn(A[i]);
    }
    if (i < NST) {
        g_K[i] = Bv[i];
        g_Kttf[i * CH] = f2tf(Bv[i]);
        g_Kth[i * CH] = __float2half_rn(Bv[i]);
    }
    if (i < 64) g_ready[i] = 0;
}

// ============================ k_powers =====================================
// 48 products x 32 CTAs (tile 32x64, 128 thr). Flag-synchronized.
__global__ void __launch_bounds__(128) k_powers() {
    const int p = blockIdx.x >> 5, q = blockIdx.x & 31;
    const int tid = threadIdx.x;

    int xid, yid, oid;
    if (p < 31) {                 // T doubling: T[o] = T[z] @ T[d-1]
        int o = p + 1;
        int d = 1 << (31 - __clz(o));
        xid = o - d; yid = d - 1; oid = o;
    } else if (p == 31) { xid = 31; yid = 31; oid = 32; }   // A^64
    else if (p == 32)   { xid = 32; yid = 31; oid = 33; }   // A^96
    else if (p == 33)   { xid = 32; yid = 32; oid = 34; }   // A^128 = P[0]
    else {                         // P doubling
        int o = p - 33;
        int d = 1 << (31 - __clz(o));
        xid = 34 + o - d; yid = 34 + d - 1; oid = 34 + o;
    }

    const float* __restrict__ X = matp(xid);
    const float* __restrict__ Y = matp(yid);

    if (tid == 0) {
        wait_ready(xid);
        if (yid != xid) wait_ready(yid);
    }
    __syncthreads();

    const int r0 = (q >> 2) * 32, c0 = (q & 3) * 64;
    __shared__ float Xs[16][36];   // [k][r]
    __shared__ float Ys[16][68];   // [k][c]
    const int tx = tid & 15, ty = tid >> 4;
    float acc[4][4];
#pragma unroll
    for (int i = 0; i < 4; i++)
#pragma unroll
        for (int j = 0; j < 4; j++) acc[i][j] = 0.f;

    for (int k0 = 0; k0 < NST; k0 += 16) {
        {   // X tile 32x16, transpose-store
            int row = tid >> 2, kb = (tid & 3) * 4;
            float4 v = *(const float4*)&X[(size_t)(r0 + row) * NST + k0 + kb];
            Xs[kb + 0][row] = v.x; Xs[kb + 1][row] = v.y;
            Xs[kb + 2][row] = v.z; Xs[kb + 3][row] = v.w;
        }
        {   // Y tile 16x64, natural
            int kk = tid >> 3, cb = (tid & 7) * 8;
            *(float4*)&Ys[kk][cb]     = *(const float4*)&Y[(size_t)(k0 + kk) * NST + c0 + cb];
            *(float4*)&Ys[kk][cb + 4] = *(const float4*)&Y[(size_t)(k0 + kk) * NST + c0 + cb + 4];
        }
        __syncthreads();
#pragma unroll
        for (int kk = 0; kk < 16; kk++) {
            float a[4], b[4];
            *(float4*)a = *(const float4*)&Xs[kk][ty * 4];
            *(float4*)b = *(const float4*)&Ys[kk][tx * 4];
#pragma unroll
            for (int i = 0; i < 4; i++)
#pragma unroll
                for (int j = 0; j < 4; j++) acc[i][j] += a[i] * b[j];
        }
        __syncthreads();
    }

    float* O = (oid < 34) ? g_T + (size_t)oid * MATSZ : g_P + (size_t)(oid - 34) * MATSZ;
    uint32_t* Otf = (oid < 34) ? g_Ttf + (size_t)oid * MATSZ : g_Ptf + (size_t)(oid - 34) * MATSZ;
#pragma unroll
    for (int i = 0; i < 4; i++) {
        size_t idx = (size_t)(r0 + ty * 4 + i) * NST + c0 + tx * 4;
        float4 v = make_float4(acc[i][0], acc[i][1], acc[i][2], acc[i][3]);
        *(float4*)&O[idx] = v;
        *(uint4*)&Otf[idx] = make_uint4(f2tf(v.x), f2tf(v.y), f2tf(v.z), f2tf(v.w));
        if (oid < 32) {
            uint2 hv = make_uint2(f2h2(v.x, v.y), f2h2(v.z, v.w));
            *(uint2*)&g_Th[(size_t)oid * MATSZ + idx] = hv;
        }
    }
    __syncthreads();
    if (tid == 0) {
        __threadfence();
        atomicAdd(&g_ready[oid], 1);
    }
}

// ============================ k_kern (K_j, j=1..31) ========================
__global__ void k_kern(const float* __restrict__ Bv) {
    int j = blockIdx.x + 1;
    const float* __restrict__ T = g_T + (size_t)(j - 1) * MATSZ;
    __shared__ float Bs[NST];
    int tid = threadIdx.x;
    if (tid < NST) Bs[tid] = Bv[tid];
    __syncthreads();
    int warp = tid >> 5, lane = tid & 31;
    for (int n = warp; n < NST; n += 8) {
        float s = 0.f;
        for (int k = lane; k < NST; k += 32) s += T[(size_t)n * NST + k] * Bs[k];
#pragma unroll
        for (int o = 16; o; o >>= 1) s += __shfl_xor_sync(0xFFFFFFFFu, s, o);
        if (!lane) {
            g_K[j * NST + n] = s;
            g_Kttf[n * CH + j] = f2tf(s);
            g_Kth[n * CH + j] = __float2half_rn(s);
        }
    }
}

// ============================ k_w2 (tf32 mma) ==============================
// grid (2, 64): w2[S][b][n0..+127] = sum_{j<32} K_j[n] f[32S+31-j][b]
__global__ void __launch_bounds__(256, 1)
k_w2(const float* __restrict__ f) {
    __shared__ uint32_t sA[4096];
    __shared__ uint32_t sB[4096];
    const uint32_t As_u = smem_u32(sA);
    const uint32_t Bs_u = smem_u32(sB);

    const int S = blockIdx.y;
    const int n0 = blockIdx.x * 128;
    const int tid = threadIdx.x;
    const int lane = tid & 31;
    const int wid = tid >> 5;
    const int wm = wid >> 2, wn = wid & 3;

    float acc[4][4][4];
#pragma unroll
    for (int mi = 0; mi < 4; mi++)
#pragma unroll
        for (int ni = 0; ni < 4; ni++)
#pragma unroll
            for (int qq = 0; qq < 4; qq++) acc[mi][ni][qq] = 0.f;

    const int a_row = wm * 64 + (lane & 7) + ((lane >> 3) & 1) * 8;
    const int a_csel = (lane >> 4) & 1;
    const int b_row = wn * 32 + (lane & 7) + ((lane >> 4) << 3);
    const int b_csel = (lane >> 3) & 1;

#pragma unroll
    for (int i = 0; i < 16; i++) {          // A: [b][j] reversed f
        int e = tid + i * 256;
        int b = e & 127, j = e >> 7;
        *(uint32_t*)((char*)sA + sw_off(b, j)) =
            f2tf(f[(size_t)(32 * S + 31 - j) * BT + b]);
    }
#pragma unroll
    for (int i = 0; i < 4; i++) {           // B: Kttf rows n0..n0+127, j<32
        int e = tid + i * 256;
        int r = e >> 3, kq = (e & 7) << 2;
        *(uint4*)((char*)sB + sw_off(r, kq)) =
            *(const uint4*)&g_Kttf[(size_t)(n0 + r) * CH + kq];
    }
    __syncthreads();
#pragma unroll
    for (int kt = 0; kt < 4; kt++) {
        uint32_t a[4][4], b[2][4];
#pragma unroll
        for (int mi = 0; mi < 4; mi++) {
            int r = a_row + mi * 16;
            int kc = kt * 8 + a_csel * 4;
            ldsm4(As_u + (uint32_t)(r * 128) + ((uint32_t)(((kc >> 2) ^ (r & 7)) << 4)),
                  a[mi][0], a[mi][1], a[mi][2], a[mi][3]);
        }
#pragma unroll
        for (int nb = 0; nb < 2; nb++) {
            int r = b_row + nb * 16;
            int kc = kt * 8 + b_csel * 4;
            ldsm4(Bs_u + (uint32_t)(r * 128) + ((uint32_t)(((kc >> 2) ^ (r & 7)) << 4)),
                  b[nb][0], b[nb][1], b[nb][2], b[nb][3]);
        }
#pragma unroll
        for (int mi = 0; mi < 4; mi++)
#pragma unroll
            for (int ni = 0; ni < 4; ni++)
                mma_tf32(acc[mi][ni], a[mi][0], a[mi][1], a[mi][2], a[mi][3],
                         b[ni >> 1][(ni & 1) * 2], b[ni >> 1][(ni & 1) * 2 + 1]);
    }

    const int er = wm * 64 + (lane >> 2);
    const int ec0 = wn * 32 + (lane & 3) * 2;
#pragma unroll
    for (int mi = 0; mi < 4; mi++) {
        int r0 = er + mi * 16;
#pragma unroll
        for (int ni = 0; ni < 4; ni++) {
            int c = ec0 + ni * 8;
            size_t i0 = ((size_t)S * BT + r0) * NST + n0 + c;
            size_t i1 = ((size_t)S * BT + r0 + 8) * NST + n0 + c;
            g_w2[i0] = acc[mi][ni][0]; g_w2[i0 + 1] = acc[mi][ni][1];
            g_w2[i1] = acc[mi][ni][2]; g_w2[i1 + 1] = acc[mi][ni][3];
            g_w2tf[i0] = f2tf(acc[mi][ni][0]); g_w2tf[i0 + 1] = f2tf(acc[mi][ni][1]);
            g_w2tf[i1] = f2tf(acc[mi][ni][2]); g_w2tf[i1 + 1] = f2tf(acc[mi][ni][3]);
        }
    }
}

// ============================ k_wg (tf32 mma) ==============================
// grid (2, 16): w[g] = A^96 w2[4g] + A^64 w2[4g+1] + A^32 w2[4g+2] + w2[4g+3]
__global__ void __launch_bounds__(256, 1)
k_wg() {
    __shared__ uint32_t sA[4096];
    __shared__ uint32_t sB[4096];
    const uint32_t As_u = smem_u32(sA);
    const uint32_t Bs_u = smem_u32(sB);

    const int g = blockIdx.y;
    const int n0 = blockIdx.x * 128;
    const int tid = threadIdx.x;
    const int lane = tid & 31;
    const int wid = tid >> 5;
    const int wm = wid >> 2, wn = wid & 3;

    float acc[4][4][4];
#pragma unroll
    for (int mi = 0; mi < 4; mi++)
#pragma unroll
        for (int ni = 0; ni < 4; ni++)
#pragma unroll
            for (int qq = 0; qq < 4; qq++) acc[mi][ni][qq] = 0.f;

    const int a_row = wm * 64 + (lane & 7) + ((lane >> 3) & 1) * 8;
    const int a_csel = (lane >> 4) & 1;
    const int b_row = wn * 32 + (lane & 7) + ((lane >> 4) << 3);
    const int b_csel = (lane >> 3) & 1;

    const int matid[3] = {33, 32, 31};   // A^96, A^64, A^32
    for (int pass = 0; pass < 3; ++pass) {
        const uint32_t* __restrict__ W = g_w2tf + (size_t)(4 * g + pass) * BT * NST;
        const uint32_t* __restrict__ Bm = g_Ttf + (size_t)matid[pass] * MATSZ;
        for (int it = 0; it < 8; ++it) {
            int k0 = it * 32;
#pragma unroll
            for (int i = 0; i < 4; i++) {
                int e = tid + i * 256;
                int r = e >> 3, kq = (e & 7) << 2;
                *(uint4*)((char*)sA + sw_off(r, kq)) =
                    *(const uint4*)&W[(size_t)r * NST + k0 + kq];
            }
#pragma unroll
            for (int i = 0; i < 4; i++) {
                int e = tid + i * 256;
                int r = e >> 3, kq = (e & 7) << 2;
                *(uint4*)((char*)sB + sw_off(r, kq)) =
                    *(const uint4*)&Bm[(size_t)(n0 + r) * NST + k0 + kq];
            }
            __syncthreads();
#pragma unroll
            for (int kt = 0; kt < 4; kt++) {
                uint32_t a[4][4], b[2][4];
#pragma unroll
                for (int mi = 0; mi < 4; mi++) {
                    int r = a_row + mi * 16;
                    int kc = kt * 8 + a_csel * 4;
                    ldsm4(As_u + (uint32_t)(r * 128) + ((uint32_t)(((kc >> 2) ^ (r & 7)) << 4)),
                          a[mi][0], a[mi][1], a[mi][2], a[mi][3]);
                }
#pragma unroll
                for (int nb = 0; nb < 2; nb++) {
                    int r = b_row + nb * 16;
                    int kc = kt * 8 + b_csel * 4;
                    ldsm4(Bs_u + (uint32_t)(r * 128) + ((uint32_t)(((kc >> 2) ^ (r & 7)) << 4)),
                          b[nb][0], b[nb][1], b[nb][2], b[nb][3]);
                }
#pragma unroll
                for (int mi = 0; mi < 4; mi++)
#pragma unroll
                    for (int ni = 0; ni < 4; ni++)
                        mma_tf32(acc[mi][ni], a[mi][0], a[mi][1], a[mi][2], a[mi][3],
                                 b[ni >> 1][(ni & 1) * 2], b[ni >> 1][(ni & 1) * 2 + 1]);
            }
            __syncthreads();
        }
    }

    const float* __restrict__ Wlast = g_w2 + (size_t)(4 * g + 3) * BT * NST;
    const int er = wm * 64 + (lane >> 2);
    const int ec0 = wn * 32 + (lane & 3) * 2;
#pragma unroll
    for (int mi = 0; mi < 4; mi++) {
        int r0 = er + mi * 16;
#pragma unroll
        for (int ni = 0; ni < 4; ni++) {
            int c = ec0 + ni * 8;
            size_t l0 = (size_t)r0 * NST + n0 + c;
            size_t l1 = (size_t)(r0 + 8) * NST + n0 + c;
            float v00 = acc[mi][ni][0] + Wlast[l0];
            float v01 = acc[mi][ni][1] + Wlast[l0 + 1];
            float v10 = acc[mi][ni][2] + Wlast[l1];
            float v11 = acc[mi][ni][3] + Wlast[l1 + 1];
            size_t i0 = (size_t)g * BT * NST + l0;
            size_t i1 = (size_t)g * BT * NST + l1;
            g_w[i0] = v00; g_w[i0 + 1] = v01;
            g_w[i1] = v10; g_w[i1 + 1] = v11;
            g_wtf[i0] = f2tf(v00); g_wtf[i0 + 1] = f2tf(v01);
            g_wtf[i1] = f2tf(v10); g_wtf[i1 + 1] = f2tf(v11);
        }
    }
}

// ============================ k_h1 (tf32 mma) ==============================
__global__ void __launch_bounds__(256, 1)
k_h1_mma() {
    extern __shared__ char smem[];
    const uint32_t As_u = smem_u32(smem);
    const uint32_t Bs_u = As_u + 16384;

    int z = blockIdx.x;
    int zr = z, g = 2;
    while (zr >= g - 1) { zr -= g - 1; g++; }
    int m = zr;
    int lag = g - 2 - m;

    const uint32_t* __restrict__ W = g_wtf + (size_t)m * BT * NST;
    const uint32_t* __restrict__ P = g_Ptf + (size_t)lag * MATSZ;
    float* __restrict__ OUT = g_part + (size_t)z * BT * NST;

    const int tid = threadIdx.x;
    const int lane = tid & 31;
    const int wid = tid >> 5;
    const int wm = wid >> 2, wn = wid & 3;

    float acc[4][8][4];
#pragma unroll
    for (int mi = 0; mi < 4; mi++)
#pragma unroll
        for (int ni = 0; ni < 8; ni++)
#pragma unroll
            for (int qq = 0; qq < 4; qq++) acc[mi][ni][qq] = 0.f;

    const int a_row = wm * 64 + (lane & 7) + ((lane >> 3) & 1) * 8;
    const int a_csel = (lane >> 4) & 1;
    const int b_row = wn * 64 + (lane & 7) + ((lane >> 4) << 3);
    const int b_csel = (lane >> 3) & 1;

    for (int it = 0; it < 8; ++it) {
        int k0 = it * 32;
#pragma unroll
        for (int i = 0; i < 4; i++) {
            int e = tid + i * 256;
            int r = e >> 3, kq = (e & 7) << 2;
            *(uint4*)(smem + sw_off(r, kq)) = *(const uint4*)&W[(size_t)r * NST + k0 + kq];
        }
#pragma unroll
        for (int i = 0; i < 8; i++) {
            int e = tid + i * 256;
            int r = e >> 3, kq = (e & 7) << 2;
            *(uint4*)(smem + 16384 + sw_off(r, kq)) = *(const uint4*)&P[(size_t)r * NST + k0 + kq];
        }
        __syncthreads();
#pragma unroll
        for (int kt = 0; kt < 4; kt++) {
            uint32_t a[4][4], b[4][4];
#pragma unroll
            for (int mi = 0; mi < 4; mi++) {
                int r = a_row + mi * 16;
                int kc = kt * 8 + a_csel * 4;
                ldsm4(As_u + (uint32_t)(r * 128) + ((uint32_t)(((kc >> 2) ^ (r & 7)) << 4)),
                      a[mi][0], a[mi][1], a[mi][2], a[mi][3]);
            }
#pragma unroll
            for (int nb = 0; nb < 4; nb++) {
                int r = b_row + nb * 16;
                int kc = kt * 8 + b_csel * 4;
                ldsm4(Bs_u + (uint32_t)(r * 128) + ((uint32_t)(((kc >> 2) ^ (r & 7)) << 4)),
                      b[nb][0], b[nb][1], b[nb][2], b[nb][3]);
            }
#pragma unroll
            for (int mi = 0; mi < 4; mi++)
#pragma unroll
                for (int ni = 0; ni < 8; ni++)
                    mma_tf32(acc[mi][ni], a[mi][0], a[mi][1], a[mi][2], a[mi][3],
                             b[ni >> 1][(ni & 1) * 2], b[ni >> 1][(ni & 1) * 2 + 1]);
        }
        __syncthreads();
    }

    const int er = wm * 64 + (lane >> 2);
    const int ec0 = wn * 64 + (lane & 3) * 2;
#pragma unroll
    for (int mi = 0; mi < 4; mi++) {
        int r0 = er + mi * 16;
#pragma unroll
        for (int ni = 0; ni < 8; ni++) {
            int c = ec0 + ni * 8;
            *(float2*)&OUT[(size_t)r0 * NST + c] =
                make_float2(acc[mi][ni][0], acc[mi][ni][1]);
            *(float2*)&OUT[(size_t)(r0 + 8) * NST + c] =
                make_float2(acc[mi][ni][2], acc[mi][ni][3]);
        }
    }
}

// ============================ k_h2 =========================================
// chunk boundary states h_g -> subchunk slot S = 4g (tf32 + fp16)
__global__ void k_h2() {
    int i = blockIdx.x * blockDim.x + threadIdx.x;
    if (i >= NG * BT * NST) return;
    int g = i / (BT * NST);
    int r = i % (BT * NST);
    float v = 0.f;
    if (g >= 1) v = g_w[(size_t)(g - 1) * BT * NST + r];
    if (g >= 2) {
        int base = (g - 1) * (g - 2) / 2;
        for (int m = 0; m <= g - 2; m++)
            v += g_part[(size_t)(base + m) * BT * NST + r];
    }
    size_t o = (size_t)(4 * g) * BT * NST + r;
    g_h2tf[o] = f2tf(v);
    g_hh[o] = __float2half_rn(v);
}

// ============================ k_hsub (tf32 mma) ============================
// grid (2, 16), param s: H[4g+s] = A^32 H[4g+s-1] + w2[4g+s-1]
__global__ void __launch_bounds__(256, 1)
k_hsub(int s) {
    __shared__ uint32_t sA[4096];
    __shared__ uint32_t sB[4096];
    const uint32_t As_u = smem_u32(sA);
    const uint32_t Bs_u = smem_u32(sB);

    const int g = blockIdx.y;
    const int n0 = blockIdx.x * 128;
    const int Sp = 4 * g + s - 1;
    const int So = Sp + 1;
    const int tid = threadIdx.x;
    const int lane = tid & 31;
    const int wid = tid >> 5;
    const int wm = wid >> 2, wn = wid & 3;

    const uint32_t* __restrict__ Hp = g_h2tf + (size_t)Sp * BT * NST;
    const uint32_t* __restrict__ Bm = g_Ttf + (size_t)31 * MATSZ;   // A^32

    float acc[4][4][4];
#pragma unroll
    for (int mi = 0; mi < 4; mi++)
#pragma unroll
        for (int ni = 0; ni < 4; ni++)
#pragma unroll
            for (int qq = 0; qq < 4; qq++) acc[mi][ni][qq] = 0.f;

    const int a_row = wm * 64 + (lane & 7) + ((lane >> 3) & 1) * 8;
    const int a_csel = (lane >> 4) & 1;
    const int b_row = wn * 32 + (lane & 7) + ((lane >> 4) << 3);
    const int b_csel = (lane >> 3) & 1;

    for (int it = 0; it < 8; ++it) {
        int k0 = it * 32;
#pragma unroll
        for (int i = 0; i < 4; i++) {
            int e = tid + i * 256;
            int r = e >> 3, kq = (e & 7) << 2;
            *(uint4*)((char*)sA + sw_off(r, kq)) =
                *(const uint4*)&Hp[(size_t)r * NST + k0 + kq];
        }
#pragma unroll
        for (int i = 0; i < 4; i++) {
            int e = tid + i * 256;
            int r = e >> 3, kq = (e & 7) << 2;
            *(uint4*)((char*)sB + sw_off(r, kq)) =
                *(const uint4*)&Bm[(size_t)(n0 + r) * NST + k0 + kq];
        }
        __syncthreads();
#pragma unroll
        for (int kt = 0; kt < 4; kt++) {
            uint32_t a[4][4], b[2][4];
#pragma unroll
            for (int mi = 0; mi < 4; mi++) {
                int r = a_row + mi * 16;
                int kc = kt * 8 + a_csel * 4;
                ldsm4(As_u + (uint32_t)(r * 128) + ((uint32_t)(((kc >> 2) ^ (r & 7)) << 4)),
                      a[mi][0], a[mi][1], a[mi][2], a[mi][3]);
            }
#pragma unroll
            for (int nb = 0; nb < 2; nb++) {
                int r = b_row + nb * 16;
                int kc = kt * 8 + b_csel * 4;
                ldsm4(Bs_u + (uint32_t)(r * 128) + ((uint32_t)(((kc >> 2) ^ (r & 7)) << 4)),
                      b[nb][0], b[nb][1], b[nb][2], b[nb][3]);
            }
#pragma unroll
            for (int mi = 0; mi < 4; mi++)
#pragma unroll
                for (int ni = 0; ni < 4; ni++)
                    mma_tf32(acc[mi][ni], a[mi][0], a[mi][1], a[mi][2], a[mi][3],
                             b[ni >> 1][(ni & 1) * 2], b[ni >> 1][(ni & 1) * 2 + 1]);
        }
        __syncthreads();
    }

    const float* __restrict__ W2 = g_w2 + (size_t)Sp * BT * NST;
    const int er = wm * 64 + (lane >> 2);
    const int ec0 = wn * 32 + (lane & 3) * 2;
#pragma unroll
    for (int mi = 0; mi < 4; mi++) {
        int r0 = er + mi * 16;
#pragma unroll
        for (int ni = 0; ni < 4; ni++) {
            int c = ec0 + ni * 8;
            size_t l0 = (size_t)r0 * NST + n0 + c;
            size_t l1 = (size_t)(r0 + 8) * NST + n0 + c;
            float v00 = acc[mi][ni][0] + W2[l0];
            float v01 = acc[mi][ni][1] + W2[l0 + 1];
            float v10 = acc[mi][ni][2] + W2[l1];
            float v11 = acc[mi][ni][3] + W2[l1 + 1];
            size_t o0 = (size_t)So * BT * NST + l0;
            size_t o1 = (size_t)So * BT * NST + l1;
            g_h2tf[o0] = f2tf(v00); g_h2tf[o0 + 1] = f2tf(v01);
            g_h2tf[o1] = f2tf(v10); g_h2tf[o1 + 1] = f2tf(v11);
            g_hh[o0] = __float2half_rn(v00); g_hh[o0 + 1] = __float2half_rn(v01);
            g_hh[o1] = __float2half_rn(v10); g_hh[o1 + 1] = __float2half_rn(v11);
        }
    }
}

// ============================ k_main (fp16) ================================
// One CTA per t. u = t&31, S = t>>5. nT = (S>0 ? 4 : 0) + 1 k64 tiles.
#define STG_BYTES 49152
#define SMEM_MAIN (3 * STG_BYTES)

__device__ __forceinline__ uint32_t sw_h(int row, int chunk) {
    return (uint32_t)(row * 128 + ((chunk ^ (row & 7)) << 4));
}

__global__ void __launch_bounds__(256, 1)
k_main_mma(const float* __restrict__ f, float* __restrict__ out) {
    extern __shared__ char smem[];
    const uint32_t s0 = smem_u32(smem);

    const int tid = threadIdx.x;
    const int lane = tid & 31;
    const int wid = tid >> 5;
    const int wm = wid >> 2;
    const int wn = wid & 3;

    const int t = blockIdx.x;
    const int S = t >> 5, u = t & 31;
    const int p1t = (S > 0) ? 4 : 0;
    const int nT = p1t + 1;

    const __half* __restrict__ Hh = g_hh + (size_t)S * BT * NST;
    const __half* __restrict__ Th = g_Th + (size_t)u * MATSZ;

    float acc[4][8][4];
#pragma unroll
    for (int mi = 0; mi < 4; mi++)
#pragma unroll
        for (int ni = 0; ni < 8; ni++)
#pragma unroll
            for (int qq = 0; qq < 4; qq++) acc[mi][ni][qq] = 0.f;

    const int a_r16 = lane & 15;
    const int a_kc = (lane >> 4) & 1;
    const int b_rb = (lane & 7) + ((lane >> 4) & 1) * 8;
    const int b_kc = (lane >> 3) & 1;

    auto prefetch = [&](int it) {
        if (it < nT) {
            int s = it - (it / 3) * 3;
            uint32_t Au = s0 + (uint32_t)(s * STG_BYTES);
            uint32_t Bu = Au + 16384;
            if (it < p1t) {
                int k0 = it * 64;
#pragma unroll
                for (int i = 0; i < 4; i++) {
                    int e = tid + i * 256;
                    int r = e >> 3, c = e & 7;
                    CP_ASYNC16(Au + sw_h(r, c), Hh + (size_t)r * NST + k0 + c * 8);
                }
#pragma unroll
                for (int i = 0; i < 8; i++) {
                    int e = tid + i * 256;
                    int r = e >> 3, c = e & 7;
                    CP_ASYNC16(Bu + sw_h(r, c), Th + (size_t)r * NST + k0 + c * 8);
                }
            } else {
#pragma unroll
                for (int i = 0; i < 8; i++) {
                    int e = tid + i * 256;
                    int r = e >> 3, c = e & 7;
                    CP_ASYNC16(Bu + sw_h(r, c), g_Kth + (size_t)r * CH + c * 8);
                }
#pragma unroll
                for (int i = 0; i < 4; i++) {
                    int e = tid + i * 256;
                    int b = e & 127, jg = e >> 7;
                    uint32_t w[4];
#pragma unroll
                    for (int p2 = 0; p2 < 4; p2++) {
                        int ja = jg * 8 + p2 * 2;
                        float v0 = (ja     <= u) ? f[(size_t)(t - ja) * BT + b] : 0.f;
                        float v1 = (ja + 1 <= u) ? f[(size_t)(t - ja - 1) * BT + b] : 0.f;
                        w[p2] = f2h2(v0, v1);
                    }
                    *(uint4*)(smem + s * STG_BYTES + sw_h(b, jg)) =
                        make_uint4(w[0], w[1], w[2], w[3]);
                }
            }
        }
        CP_COMMIT();
    };

    prefetch(0);
    prefetch(1);
    for (int it = 0; it < nT; ++it) {
        CP_WAIT1();
        __syncthreads();

        int s = it - (it / 3) * 3;
        uint32_t Au = s0 + (uint32_t)(s * STG_BYTES);
        uint32_t Bu = Au + 16384;
#pragma unroll
        for (int kt = 0; kt < 4; kt++) {
            uint32_t a[4][4], b[4][4];
#pragma unroll
            for (int mi = 0; mi < 4; mi++) {
                int r = wm * 64 + mi * 16 + a_r16;
                int c = kt * 2 + a_kc;
                ldsm4(Au + sw_h(r, c), a[mi][0], a[mi][1], a[mi][2], a[mi][3]);
            }
#pragma unroll
            for (int nbp = 0; nbp < 4; nbp++) {
                int r = wn * 64 + nbp * 16 + b_rb;
                int c = kt * 2 + b_kc;
                ldsm4(Bu + sw_h(r, c), b[nbp][0], b[nbp][1], b[nbp][2], b[nbp][3]);
            }
#pragma unroll
            for (int mi = 0; mi < 4; mi++)
#pragma unroll
                for (int n8 = 0; n8 < 8; n8++)
                    mma_f16(acc[mi][n8], a[mi][0], a[mi][1], a[mi][2], a[mi][3],
                            b[n8 >> 1][(n8 & 1) * 2], b[n8 >> 1][(n8 & 1) * 2 + 1]);
        }
        prefetch(it + 2);
    }

    float* __restrict__ o = out + (size_t)t * BT * NST;
    const int er = wm * 64 + (lane >> 2);
    const int ec0 = wn * 64 + (lane & 3) * 2;
#pragma unroll
    for (int mi = 0; mi < 4; mi++) {
        int r0 = er + mi * 16;
#pragma unroll
        for (int n8 = 0; n8 < 8; n8++) {
            int c = ec0 + n8 * 8;
            *(float2*)&o[(size_t)r0 * NST + c] =
                make_float2(acc[mi][n8][0], acc[mi][n8][1]);
            *(float2*)&o[(size_t)(r0 + 8) * NST + c] =
                make_float2(acc[mi][n8][2], acc[mi][n8][3]);
        }
    }
}

// ---------------------------------------------------------------------------
extern "C" void kernel_launch(void* const* d_in, const int* in_sizes, int n_in,
                              void* d_out, int out_size) {
    const float* f = nullptr;
    const float* A = nullptr;
    const float* Bv = nullptr;
    for (int i = 0; i < n_in; i++) {
        if (in_sizes[i] == LSEQ * BT) f = (const float*)d_in[i];
        else if (in_sizes[i] == NST * NST) A = (const float*)d_in[i];
        else if (in_sizes[i] == NST) Bv = (const float*)d_in[i];
    }
    float* out = (float*)d_out;

    cudaFuncSetAttribute(k_main_mma, cudaFuncAttributeMaxDynamicSharedMemorySize,
                         SMEM_MAIN);
    cudaFuncSetAttribute(k_h1_mma, cudaFuncAttributeMaxDynamicSharedMemorySize,
                         49152);

    k_init<<<256, 256>>>(A, Bv);
    k_powers<<<48 * 32, 128>>>();
    k_kern<<<31, 256>>>(Bv);
    k_w2<<<dim3(2, NSUB), 256>>>(f);
    k_wg<<<dim3(2, NG), 256>>>();
    k_h1_mma<<<NPAIR, 256, 49152>>>();
    k_h2<<<(NG * BT * NST + 255) / 256, 256>>>();
    k_hsub<<<dim3(2, NG), 256>>>(1);
    k_hsub<<<dim3(2, NG), 256>>>(2);
    k_hsub<<<dim3(2, NG), 256>>>(3);
    k_main_mma<<<LSEQ, 256, SMEM_MAIN>>>(f, out);
    (void)out_size;
}

// round 12
// speedup vs baseline: 1.4798x; 1.0419x over previous
#include <cuda_runtime.h>
#include <cuda_fp16.h>
#include <cstdint>

// ---------------------------------------------------------------------------
// HiPPO-LegT full-state scan as parallel GEMMs (subchunk-32 restructure).
// out[t] = A^{u+1} H_S + sum_{j<=u} K_j f[t-j], u = t mod 32, S = t/32.
// Round 11: k_main re-shaped for TRUE 2 CTAs/SM: 128-thread CTAs (4 warps),
// warp tile stays 64x64 (ldsm:mma ratio preserved), CTA tile 128x128,
// 3-stage 32KB cp.async ring -> 96KB/CTA smem, <=256-reg cap (no spills).
// ---------------------------------------------------------------------------

#define LSEQ 2048
#define BT   128
#define NST  256
#define CH   128
#define NG   16
#define NSUB 64
#define NPAIR 105
#define MATSZ (NST * NST)

// matrix ids: 0..31 = T[i] = A^{i+1}; 32 = A^64; 33 = A^96; 34+r = P[r]
__device__ float    g_T[34 * MATSZ];
__device__ uint32_t g_Ttf[34 * MATSZ];
__device__ __half   g_Th[32 * MATSZ];
__device__ float    g_P[15 * MATSZ];
__device__ uint32_t g_Ptf[15 * MATSZ];
__device__ float    g_K[32 * NST];
__device__ uint32_t g_Kttf[NST * CH];
__device__ __half   g_Kth[NST * CH];
__device__ float    g_w2[NSUB * BT * NST];
__device__ uint32_t g_w2tf[NSUB * BT * NST];
__device__ float    g_w[NG * BT * NST];
__device__ uint32_t g_wtf[NG * BT * NST];
__device__ float    g_part[NPAIR * BT * NST];
__device__ uint32_t g_h2tf[NSUB * BT * NST];
__device__ __half   g_hh[NSUB * BT * NST];
__device__ int      g_ready[64];

// ============================ helpers ======================================
__device__ __forceinline__ uint32_t smem_u32(const void* p) {
    uint32_t a;
    asm("{ .reg .u64 t; cvta.to.shared.u64 t, %1; cvt.u32.u64 %0, t; }"
        : "=r"(a) : "l"(p));
    return a;
}
__device__ __forceinline__ uint32_t f2tf(float x) {
    uint32_t r;
    asm("cvt.rna.tf32.f32 %0, %1;" : "=r"(r) : "f"(x));
    return r;
}
__device__ __forceinline__ uint32_t f2h2(float lo, float hi) {
    __half2 h = __floats2half2_rn(lo, hi);
    return *(uint32_t*)&h;
}
__device__ __forceinline__ void ldsm4(uint32_t addr, uint32_t& r0, uint32_t& r1,
                                      uint32_t& r2, uint32_t& r3) {
    asm volatile("ldmatrix.sync.aligned.m8n8.x4.shared.b16 {%0,%1,%2,%3}, [%4];"
                 : "=r"(r0), "=r"(r1), "=r"(r2), "=r"(r3) : "r"(addr));
}
__device__ __forceinline__ void mma_tf32(float* c, uint32_t a0, uint32_t a1,
                                         uint32_t a2, uint32_t a3,
                                         uint32_t b0, uint32_t b1) {
    asm volatile(
        "mma.sync.aligned.m16n8k8.row.col.f32.tf32.tf32.f32 "
        "{%0,%1,%2,%3}, {%4,%5,%6,%7}, {%8,%9}, {%0,%1,%2,%3};"
        : "+f"(c[0]), "+f"(c[1]), "+f"(c[2]), "+f"(c[3])
        : "r"(a0), "r"(a1), "r"(a2), "r"(a3), "r"(b0), "r"(b1));
}
__device__ __forceinline__ void mma_f16(float* c, uint32_t a0, uint32_t a1,
                                        uint32_t a2, uint32_t a3,
                                        uint32_t b0, uint32_t b1) {
    asm volatile(
        "mma.sync.aligned.m16n8k16.row.col.f32.f16.f16.f32 "
        "{%0,%1,%2,%3}, {%4,%5,%6,%7}, {%8,%9}, {%0,%1,%2,%3};"
        : "+f"(c[0]), "+f"(c[1]), "+f"(c[2]), "+f"(c[3])
        : "r"(a0), "r"(a1), "r"(a2), "r"(a3), "r"(b0), "r"(b1));
}
#define CP_ASYNC16(dst, src) \
    asm volatile("cp.async.cg.shared.global [%0], [%1], 16;" \
                 :: "r"(dst), "l"(src) : "memory")
#define CP_COMMIT() asm volatile("cp.async.commit_group;" ::: "memory")
#define CP_WAIT1()  asm volatile("cp.async.wait_group 1;" ::: "memory")

// tf32 swizzle: 32 floats (128B) per row
__device__ __forceinline__ uint32_t sw_off(int row, int k) {
    return (uint32_t)(row * 128 + ((((k >> 2) ^ (row & 7)) << 4) | ((k & 3) << 2)));
}
__device__ __forceinline__ void wait_ready(int id) {
    if (id == 0) return;
    int v;
    do {
        asm volatile("ld.acquire.gpu.global.b32 %0, [%1];"
                     : "=r"(v) : "l"(g_ready + id));
        if (v < 32) __nanosleep(100);
    } while (v < 32);
}
__device__ __forceinline__ const float* matp(int id) {
    return (id < 34) ? g_T + (size_t)id * MATSZ : g_P + (size_t)(id - 34) * MATSZ;
}

// ============================ k_init =======================================
__global__ void k_init(const float* __restrict__ A, const float* __restrict__ Bv) {
    int i = blockIdx.x * blockDim.x + threadIdx.x;
    if (i < MATSZ) {
        g_T[i] = A[i];
        g_Ttf[i] = f2tf(A[i]);
        g_Th[i] = __float2half_rn(A[i]);
    }
    if (i < NST) {
        g_K[i] = Bv[i];
        g_Kttf[i * CH] = f2tf(Bv[i]);
        g_Kth[i * CH] = __float2half_rn(Bv[i]);
    }
    if (i < 64) g_ready[i] = 0;
}

// ============================ k_powers =====================================
__global__ void __launch_bounds__(128) k_powers() {
    const int p = blockIdx.x >> 5, q = blockIdx.x & 31;
    const int tid = threadIdx.x;

    int xid, yid, oid;
    if (p < 31) {
        int o = p + 1;
        int d = 1 << (31 - __clz(o));
        xid = o - d; yid = d - 1; oid = o;
    } else if (p == 31) { xid = 31; yid = 31; oid = 32; }
    else if (p == 32)   { xid = 32; yid = 31; oid = 33; }
    else if (p == 33)   { xid = 32; yid = 32; oid = 34; }
    else {
        int o = p - 33;
        int d = 1 << (31 - __clz(o));
        xid = 34 + o - d; yid = 34 + d - 1; oid = 34 + o;
    }

    const float* __restrict__ X = matp(xid);
    const float* __restrict__ Y = matp(yid);

    if (tid == 0) {
        wait_ready(xid);
        if (yid != xid) wait_ready(yid);
    }
    __syncthreads();

    const int r0 = (q >> 2) * 32, c0 = (q & 3) * 64;
    __shared__ float Xs[16][36];
    __shared__ float Ys[16][68];
    const int tx = tid & 15, ty = tid >> 4;
    float acc[4][4];
#pragma unroll
    for (int i = 0; i < 4; i++)
#pragma unroll
        for (int j = 0; j < 4; j++) acc[i][j] = 0.f;

    for (int k0 = 0; k0 < NST; k0 += 16) {
        {
            int row = tid >> 2, kb = (tid & 3) * 4;
            float4 v = *(const float4*)&X[(size_t)(r0 + row) * NST + k0 + kb];
            Xs[kb + 0][row] = v.x; Xs[kb + 1][row] = v.y;
            Xs[kb + 2][row] = v.z; Xs[kb + 3][row] = v.w;
        }
        {
            int kk = tid >> 3, cb = (tid & 7) * 8;
            *(float4*)&Ys[kk][cb]     = *(const float4*)&Y[(size_t)(k0 + kk) * NST + c0 + cb];
            *(float4*)&Ys[kk][cb + 4] = *(const float4*)&Y[(size_t)(k0 + kk) * NST + c0 + cb + 4];
        }
        __syncthreads();
#pragma unroll
        for (int kk = 0; kk < 16; kk++) {
            float a[4], b[4];
            *(float4*)a = *(const float4*)&Xs[kk][ty * 4];
            *(float4*)b = *(const float4*)&Ys[kk][tx * 4];
#pragma unroll
            for (int i = 0; i < 4; i++)
#pragma unroll
                for (int j = 0; j < 4; j++) acc[i][j] += a[i] * b[j];
        }
        __syncthreads();
    }

    float* O = (oid < 34) ? g_T + (size_t)oid * MATSZ : g_P + (size_t)(oid - 34) * MATSZ;
    uint32_t* Otf = (oid < 34) ? g_Ttf + (size_t)oid * MATSZ : g_Ptf + (size_t)(oid - 34) * MATSZ;
#pragma unroll
    for (int i = 0; i < 4; i++) {
        size_t idx = (size_t)(r0 + ty * 4 + i) * NST + c0 + tx * 4;
        float4 v = make_float4(acc[i][0], acc[i][1], acc[i][2], acc[i][3]);
        *(float4*)&O[idx] = v;
        *(uint4*)&Otf[idx] = make_uint4(f2tf(v.x), f2tf(v.y), f2tf(v.z), f2tf(v.w));
        if (oid < 32) {
            uint2 hv = make_uint2(f2h2(v.x, v.y), f2h2(v.z, v.w));
            *(uint2*)&g_Th[(size_t)oid * MATSZ + idx] = hv;
        }
    }
    __syncthreads();
    if (tid == 0) {
        __threadfence();
        atomicAdd(&g_ready[oid], 1);
    }
}

// ============================ k_kern =======================================
__global__ void k_kern(const float* __restrict__ Bv) {
    int j = blockIdx.x + 1;
    const float* __restrict__ T = g_T + (size_t)(j - 1) * MATSZ;
    __shared__ float Bs[NST];
    int tid = threadIdx.x;
    if (tid < NST) Bs[tid] = Bv[tid];
    __syncthreads();
    int warp = tid >> 5, lane = tid & 31;
    for (int n = warp; n < NST; n += 8) {
        float s = 0.f;
        for (int k = lane; k < NST; k += 32) s += T[(size_t)n * NST + k] * Bs[k];
#pragma unroll
        for (int o = 16; o; o >>= 1) s += __shfl_xor_sync(0xFFFFFFFFu, s, o);
        if (!lane) {
            g_K[j * NST + n] = s;
            g_Kttf[n * CH + j] = f2tf(s);
            g_Kth[n * CH + j] = __float2half_rn(s);
        }
    }
}

// ============================ k_w2 (tf32 mma) ==============================
__global__ void __launch_bounds__(256, 1)
k_w2(const float* __restrict__ f) {
    __shared__ uint32_t sA[4096];
    __shared__ uint32_t sB[4096];
    const uint32_t As_u = smem_u32(sA);
    const uint32_t Bs_u = smem_u32(sB);

    const int S = blockIdx.y;
    const int n0 = blockIdx.x * 128;
    const int tid = threadIdx.x;
    const int lane = tid & 31;
    const int wid = tid >> 5;
    const int wm = wid >> 2, wn = wid & 3;

    float acc[4][4][4];
#pragma unroll
    for (int mi = 0; mi < 4; mi++)
#pragma unroll
        for (int ni = 0; ni < 4; ni++)
#pragma unroll
            for (int qq = 0; qq < 4; qq++) acc[mi][ni][qq] = 0.f;

    const int a_row = wm * 64 + (lane & 7) + ((lane >> 3) & 1) * 8;
    const int a_csel = (lane >> 4) & 1;
    const int b_row = wn * 32 + (lane & 7) + ((lane >> 4) << 3);
    const int b_csel = (lane >> 3) & 1;

#pragma unroll
    for (int i = 0; i < 16; i++) {
        int e = tid + i * 256;
        int b = e & 127, j = e >> 7;
        *(uint32_t*)((char*)sA + sw_off(b, j)) =
            f2tf(f[(size_t)(32 * S + 31 - j) * BT + b]);
    }
#pragma unroll
    for (int i = 0; i < 4; i++) {
        int e = tid + i * 256;
        int r = e >> 3, kq = (e & 7) << 2;
        *(uint4*)((char*)sB + sw_off(r, kq)) =
            *(const uint4*)&g_Kttf[(size_t)(n0 + r) * CH + kq];
    }
    __syncthreads();
#pragma unroll
    for (int kt = 0; kt < 4; kt++) {
        uint32_t a[4][4], b[2][4];
#pragma unroll
        for (int mi = 0; mi < 4; mi++) {
            int r = a_row + mi * 16;
            int kc = kt * 8 + a_csel * 4;
            ldsm4(As_u + (uint32_t)(r * 128) + ((uint32_t)(((kc >> 2) ^ (r & 7)) << 4)),
                  a[mi][0], a[mi][1], a[mi][2], a[mi][3]);
        }
#pragma unroll
        for (int nb = 0; nb < 2; nb++) {
            int r = b_row + nb * 16;
            int kc = kt * 8 + b_csel * 4;
            ldsm4(Bs_u + (uint32_t)(r * 128) + ((uint32_t)(((kc >> 2) ^ (r & 7)) << 4)),
                  b[nb][0], b[nb][1], b[nb][2], b[nb][3]);
        }
#pragma unroll
        for (int mi = 0; mi < 4; mi++)
#pragma unroll
            for (int ni = 0; ni < 4; ni++)
                mma_tf32(acc[mi][ni], a[mi][0], a[mi][1], a[mi][2], a[mi][3],
                         b[ni >> 1][(ni & 1) * 2], b[ni >> 1][(ni & 1) * 2 + 1]);
    }

    const int er = wm * 64 + (lane >> 2);
    const int ec0 = wn * 32 + (lane & 3) * 2;
#pragma unroll
    for (int mi = 0; mi < 4; mi++) {
        int r0 = er + mi * 16;
#pragma unroll
        for (int ni = 0; ni < 4; ni++) {
            int c = ec0 + ni * 8;
            size_t i0 = ((size_t)S * BT + r0) * NST + n0 + c;
            size_t i1 = ((size_t)S * BT + r0 + 8) * NST + n0 + c;
            g_w2[i0] = acc[mi][ni][0]; g_w2[i0 + 1] = acc[mi][ni][1];
            g_w2[i1] = acc[mi][ni][2]; g_w2[i1 + 1] = acc[mi][ni][3];
            g_w2tf[i0] = f2tf(acc[mi][ni][0]); g_w2tf[i0 + 1] = f2tf(acc[mi][ni][1]);
            g_w2tf[i1] = f2tf(acc[mi][ni][2]); g_w2tf[i1 + 1] = f2tf(acc[mi][ni][3]);
        }
    }
}

// ============================ k_wg (tf32 mma) ==============================
__global__ void __launch_bounds__(256, 1)
k_wg() {
    __shared__ uint32_t sA[4096];
    __shared__ uint32_t sB[4096];
    const uint32_t As_u = smem_u32(sA);
    const uint32_t Bs_u = smem_u32(sB);

    const int g = blockIdx.y;
    const int n0 = blockIdx.x * 128;
    const int tid = threadIdx.x;
    const int lane = tid & 31;
    const int wid = tid >> 5;
    const int wm = wid >> 2, wn = wid & 3;

    float acc[4][4][4];
#pragma unroll
    for (int mi = 0; mi < 4; mi++)
#pragma unroll
        for (int ni = 0; ni < 4; ni++)
#pragma unroll
            for (int qq = 0; qq < 4; qq++) acc[mi][ni][qq] = 0.f;

    const int a_row = wm * 64 + (lane & 7) + ((lane >> 3) & 1) * 8;
    const int a_csel = (lane >> 4) & 1;
    const int b_row = wn * 32 + (lane & 7) + ((lane >> 4) << 3);
    const int b_csel = (lane >> 3) & 1;

    const int matid[3] = {33, 32, 31};
    for (int pass = 0; pass < 3; ++pass) {
        const uint32_t* __restrict__ W = g_w2tf + (size_t)(4 * g + pass) * BT * NST;
        const uint32_t* __restrict__ Bm = g_Ttf + (size_t)matid[pass] * MATSZ;
        for (int it = 0; it < 8; ++it) {
            int k0 = it * 32;
#pragma unroll
            for (int i = 0; i < 4; i++) {
                int e = tid + i * 256;
                int r = e >> 3, kq = (e & 7) << 2;
                *(uint4*)((char*)sA + sw_off(r, kq)) =
                    *(const uint4*)&W[(size_t)r * NST + k0 + kq];
            }
#pragma unroll
            for (int i = 0; i < 4; i++) {
                int e = tid + i * 256;
                int r = e >> 3, kq = (e & 7) << 2;
                *(uint4*)((char*)sB + sw_off(r, kq)) =
                    *(const uint4*)&Bm[(size_t)(n0 + r) * NST + k0 + kq];
            }
            __syncthreads();
#pragma unroll
            for (int kt = 0; kt < 4; kt++) {
                uint32_t a[4][4], b[2][4];
#pragma unroll
                for (int mi = 0; mi < 4; mi++) {
                    int r = a_row + mi * 16;
                    int kc = kt * 8 + a_csel * 4;
                    ldsm4(As_u + (uint32_t)(r * 128) + ((uint32_t)(((kc >> 2) ^ (r & 7)) << 4)),
                          a[mi][0], a[mi][1], a[mi][2], a[mi][3]);
                }
#pragma unroll
                for (int nb = 0; nb < 2; nb++) {
                    int r = b_row + nb * 16;
                    int kc = kt * 8 + b_csel * 4;
                    ldsm4(Bs_u + (uint32_t)(r * 128) + ((uint32_t)(((kc >> 2) ^ (r & 7)) << 4)),
                          b[nb][0], b[nb][1], b[nb][2], b[nb][3]);
                }
#pragma unroll
                for (int mi = 0; mi < 4; mi++)
#pragma unroll
                    for (int ni = 0; ni < 4; ni++)
                        mma_tf32(acc[mi][ni], a[mi][0], a[mi][1], a[mi][2], a[mi][3],
                                 b[ni >> 1][(ni & 1) * 2], b[ni >> 1][(ni & 1) * 2 + 1]);
            }
            __syncthreads();
        }
    }

    const float* __restrict__ Wlast = g_w2 + (size_t)(4 * g + 3) * BT * NST;
    const int er = wm * 64 + (lane >> 2);
    const int ec0 = wn * 32 + (lane & 3) * 2;
#pragma unroll
    for (int mi = 0; mi < 4; mi++) {
        int r0 = er + mi * 16;
#pragma unroll
        for (int ni = 0; ni < 4; ni++) {
            int c = ec0 + ni * 8;
            size_t l0 = (size_t)r0 * NST + n0 + c;
            size_t l1 = (size_t)(r0 + 8) * NST + n0 + c;
            float v00 = acc[mi][ni][0] + Wlast[l0];
            float v01 = acc[mi][ni][1] + Wlast[l0 + 1];
            float v10 = acc[mi][ni][2] + Wlast[l1];
            float v11 = acc[mi][ni][3] + Wlast[l1 + 1];
            size_t i0 = (size_t)g * BT * NST + l0;
            size_t i1 = (size_t)g * BT * NST + l1;
            g_w[i0] = v00; g_w[i0 + 1] = v01;
            g_w[i1] = v10; g_w[i1 + 1] = v11;
            g_wtf[i0] = f2tf(v00); g_wtf[i0 + 1] = f2tf(v01);
            g_wtf[i1] = f2tf(v10); g_wtf[i1 + 1] = f2tf(v11);
        }
    }
}

// ============================ k_h1 (tf32 mma) ==============================
__global__ void __launch_bounds__(256, 1)
k_h1_mma() {
    extern __shared__ char smem[];
    const uint32_t As_u = smem_u32(smem);
    const uint32_t Bs_u = As_u + 16384;

    int z = blockIdx.x;
    int zr = z, g = 2;
    while (zr >= g - 1) { zr -= g - 1; g++; }
    int m = zr;
    int lag = g - 2 - m;

    const uint32_t* __restrict__ W = g_wtf + (size_t)m * BT * NST;
    const uint32_t* __restrict__ P = g_Ptf + (size_t)lag * MATSZ;
    float* __restrict__ OUT = g_part + (size_t)z * BT * NST;

    const int tid = threadIdx.x;
    const int lane = tid & 31;
    const int wid = tid >> 5;
    const int wm = wid >> 2, wn = wid & 3;

    float acc[4][8][4];
#pragma unroll
    for (int mi = 0; mi < 4; mi++)
#pragma unroll
        for (int ni = 0; ni < 8; ni++)
#pragma unroll
            for (int qq = 0; qq < 4; qq++) acc[mi][ni][qq] = 0.f;

    const int a_row = wm * 64 + (lane & 7) + ((lane >> 3) & 1) * 8;
    const int a_csel = (lane >> 4) & 1;
    const int b_row = wn * 64 + (lane & 7) + ((lane >> 4) << 3);
    const int b_csel = (lane >> 3) & 1;

    for (int it = 0; it < 8; ++it) {
        int k0 = it * 32;
#pragma unroll
        for (int i = 0; i < 4; i++) {
            int e = tid + i * 256;
            int r = e >> 3, kq = (e & 7) << 2;
            *(uint4*)(smem + sw_off(r, kq)) = *(const uint4*)&W[(size_t)r * NST + k0 + kq];
        }
#pragma unroll
        for (int i = 0; i < 8; i++) {
            int e = tid + i * 256;
            int r = e >> 3, kq = (e & 7) << 2;
            *(uint4*)(smem + 16384 + sw_off(r, kq)) = *(const uint4*)&P[(size_t)r * NST + k0 + kq];
        }
        __syncthreads();
#pragma unroll
        for (int kt = 0; kt < 4; kt++) {
            uint32_t a[4][4], b[4][4];
#pragma unroll
            for (int mi = 0; mi < 4; mi++) {
                int r = a_row + mi * 16;
                int kc = kt * 8 + a_csel * 4;
                ldsm4(As_u + (uint32_t)(r * 128) + ((uint32_t)(((kc >> 2) ^ (r & 7)) << 4)),
                      a[mi][0], a[mi][1], a[mi][2], a[mi][3]);
            }
#pragma unroll
            for (int nb = 0; nb < 4; nb++) {
                int r = b_row + nb * 16;
                int kc = kt * 8 + b_csel * 4;
                ldsm4(Bs_u + (uint32_t)(r * 128) + ((uint32_t)(((kc >> 2) ^ (r & 7)) << 4)),
                      b[nb][0], b[nb][1], b[nb][2], b[nb][3]);
            }
#pragma unroll
            for (int mi = 0; mi < 4; mi++)
#pragma unroll
                for (int ni = 0; ni < 8; ni++)
                    mma_tf32(acc[mi][ni], a[mi][0], a[mi][1], a[mi][2], a[mi][3],
                             b[ni >> 1][(ni & 1) * 2], b[ni >> 1][(ni & 1) * 2 + 1]);
        }
        __syncthreads();
    }

    const int er = wm * 64 + (lane >> 2);
    const int ec0 = wn * 64 + (lane & 3) * 2;
#pragma unroll
    for (int mi = 0; mi < 4; mi++) {
        int r0 = er + mi * 16;
#pragma unroll
        for (int ni = 0; ni < 8; ni++) {
            int c = ec0 + ni * 8;
            *(float2*)&OUT[(size_t)r0 * NST + c] =
                make_float2(acc[mi][ni][0], acc[mi][ni][1]);
            *(float2*)&OUT[(size_t)(r0 + 8) * NST + c] =
                make_float2(acc[mi][ni][2], acc[mi][ni][3]);
        }
    }
}

// ============================ k_h2 =========================================
__global__ void k_h2() {
    int i = blockIdx.x * blockDim.x + threadIdx.x;
    if (i >= NG * BT * NST) return;
    int g = i / (BT * NST);
    int r = i % (BT * NST);
    float v = 0.f;
    if (g >= 1) v = g_w[(size_t)(g - 1) * BT * NST + r];
    if (g >= 2) {
        int base = (g - 1) * (g - 2) / 2;
        for (int m = 0; m <= g - 2; m++)
            v += g_part[(size_t)(base + m) * BT * NST + r];
    }
    size_t o = (size_t)(4 * g) * BT * NST + r;
    g_h2tf[o] = f2tf(v);
    g_hh[o] = __float2half_rn(v);
}

// ============================ k_hsub (tf32 mma) ============================
__global__ void __launch_bounds__(256, 1)
k_hsub(int s) {
    __shared__ uint32_t sA[4096];
    __shared__ uint32_t sB[4096];
    const uint32_t As_u = smem_u32(sA);
    const uint32_t Bs_u = smem_u32(sB);

    const int g = blockIdx.y;
    const int n0 = blockIdx.x * 128;
    const int Sp = 4 * g + s - 1;
    const int So = Sp + 1;
    const int tid = threadIdx.x;
    const int lane = tid & 31;
    const int wid = tid >> 5;
    const int wm = wid >> 2, wn = wid & 3;

    const uint32_t* __restrict__ Hp = g_h2tf + (size_t)Sp * BT * NST;
    const uint32_t* __restrict__ Bm = g_Ttf + (size_t)31 * MATSZ;

    float acc[4][4][4];
#pragma unroll
    for (int mi = 0; mi < 4; mi++)
#pragma unroll
        for (int ni = 0; ni < 4; ni++)
#pragma unroll
            for (int qq = 0; qq < 4; qq++) acc[mi][ni][qq] = 0.f;

    const int a_row = wm * 64 + (lane & 7) + ((lane >> 3) & 1) * 8;
    const int a_csel = (lane >> 4) & 1;
    const int b_row = wn * 32 + (lane & 7) + ((lane >> 4) << 3);
    const int b_csel = (lane >> 3) & 1;

    for (int it = 0; it < 8; ++it) {
        int k0 = it * 32;
#pragma unroll
        for (int i = 0; i < 4; i++) {
            int e = tid + i * 256;
            int r = e >> 3, kq = (e & 7) << 2;
            *(uint4*)((char*)sA + sw_off(r, kq)) =
                *(const uint4*)&Hp[(size_t)r * NST + k0 + kq];
        }
#pragma unroll
        for (int i = 0; i < 4; i++) {
            int e = tid + i * 256;
            int r = e >> 3, kq = (e & 7) << 2;
            *(uint4*)((char*)sB + sw_off(r, kq)) =
                *(const uint4*)&Bm[(size_t)(n0 + r) * NST + k0 + kq];
        }
        __syncthreads();
#pragma unroll
        for (int kt = 0; kt < 4; kt++) {
            uint32_t a[4][4], b[2][4];
#pragma unroll
            for (int mi = 0; mi < 4; mi++) {
                int r = a_row + mi * 16;
                int kc = kt * 8 + a_csel * 4;
                ldsm4(As_u + (uint32_t)(r * 128) + ((uint32_t)(((kc >> 2) ^ (r & 7)) << 4)),
                      a[mi][0], a[mi][1], a[mi][2], a[mi][3]);
            }
#pragma unroll
            for (int nb = 0; nb < 2; nb++) {
                int r = b_row + nb * 16;
                int kc = kt * 8 + b_csel * 4;
                ldsm4(Bs_u + (uint32_t)(r * 128) + ((uint32_t)(((kc >> 2) ^ (r & 7)) << 4)),
                      b[nb][0], b[nb][1], b[nb][2], b[nb][3]);
            }
#pragma unroll
            for (int mi = 0; mi < 4; mi++)
#pragma unroll
                for (int ni = 0; ni < 4; ni++)
                    mma_tf32(acc[mi][ni], a[mi][0], a[mi][1], a[mi][2], a[mi][3],
                             b[ni >> 1][(ni & 1) * 2], b[ni >> 1][(ni & 1) * 2 + 1]);
        }
        __syncthreads();
    }

    const float* __restrict__ W2 = g_w2 + (size_t)Sp * BT * NST;
    const int er = wm * 64 + (lane >> 2);
    const int ec0 = wn * 32 + (lane & 3) * 2;
#pragma unroll
    for (int mi = 0; mi < 4; mi++) {
        int r0 = er + mi * 16;
#pragma unroll
        for (int ni = 0; ni < 4; ni++) {
            int c = ec0 + ni * 8;
            size_t l0 = (size_t)r0 * NST + n0 + c;
            size_t l1 = (size_t)(r0 + 8) * NST + n0 + c;
            float v00 = acc[mi][ni][0] + W2[l0];
            float v01 = acc[mi][ni][1] + W2[l0 + 1];
            float v10 = acc[mi][ni][2] + W2[l1];
            float v11 = acc[mi][ni][3] + W2[l1 + 1];
            size_t o0 = (size_t)So * BT * NST + l0;
            size_t o1 = (size_t)So * BT * NST + l1;
            g_h2tf[o0] = f2tf(v00); g_h2tf[o0 + 1] = f2tf(v01);
            g_h2tf[o1] = f2tf(v10); g_h2tf[o1 + 1] = f2tf(v11);
            g_hh[o0] = __float2half_rn(v00); g_hh[o0 + 1] = __float2half_rn(v01);
            g_hh[o1] = __float2half_rn(v10); g_hh[o1 + 1] = __float2half_rn(v11);
        }
    }
}

// ============================ k_main (fp16, 128thr, 2 CTA/SM) ==============
// grid (2, LSEQ): CTA (n-half, t). 4 warps 2x2, warp tile 64x64.
// Stage = A 16KB + B 16KB = 32KB; 3 stages = 96KB -> 2 CTAs/SM.
#define STG_BYTES 32768
#define SMEM_MAIN (3 * STG_BYTES)

__device__ __forceinline__ uint32_t sw_h(int row, int chunk) {
    return (uint32_t)(row * 128 + ((chunk ^ (row & 7)) << 4));
}

__global__ void __launch_bounds__(128, 2)
k_main_mma(const float* __restrict__ f, float* __restrict__ out) {
    extern __shared__ char smem[];
    const uint32_t s0 = smem_u32(smem);

    const int tid = threadIdx.x;
    const int lane = tid & 31;
    const int wid = tid >> 5;          // 0..3
    const int wm = wid >> 1;           // 0..1
    const int wn = wid & 1;            // 0..1

    const int t = blockIdx.y;
    const int n0 = blockIdx.x * 128;
    const int S = t >> 5, u = t & 31;
    const int p1t = (S > 0) ? 4 : 0;
    const int nT = p1t + 1;

    const __half* __restrict__ Hh = g_hh + (size_t)S * BT * NST;
    const __half* __restrict__ Th = g_Th + (size_t)u * MATSZ;

    float acc[4][8][4];
#pragma unroll
    for (int mi = 0; mi < 4; mi++)
#pragma unroll
        for (int ni = 0; ni < 8; ni++)
#pragma unroll
            for (int qq = 0; qq < 4; qq++) acc[mi][ni][qq] = 0.f;

    const int a_r16 = lane & 15;
    const int a_kc = (lane >> 4) & 1;
    const int b_rb = (lane & 7) + ((lane >> 4) & 1) * 8;
    const int b_kc = (lane >> 3) & 1;

    auto prefetch = [&](int it) {
        if (it < nT) {
            int s = it - (it / 3) * 3;
            uint32_t Au = s0 + (uint32_t)(s * STG_BYTES);
            uint32_t Bu = Au + 16384;
            if (it < p1t) {
                int k0 = it * 64;
#pragma unroll
                for (int i = 0; i < 8; i++) {      // A = H : 128 rows x 8 chunks
                    int e = tid + i * 128;
                    int r = e >> 3, c = e & 7;
                    CP_ASYNC16(Au + sw_h(r, c), Hh + (size_t)r * NST + k0 + c * 8);
                }
#pragma unroll
                for (int i = 0; i < 8; i++) {      // B = T rows n0..n0+127
                    int e = tid + i * 128;
                    int r = e >> 3, c = e & 7;
                    CP_ASYNC16(Bu + sw_h(r, c),
                               Th + (size_t)(n0 + r) * NST + k0 + c * 8);
                }
            } else {
#pragma unroll
                for (int i = 0; i < 8; i++) {      // B = Kt rows n0..n0+127
                    int e = tid + i * 128;
                    int r = e >> 3, c = e & 7;
                    CP_ASYNC16(Bu + sw_h(r, c),
                               g_Kth + (size_t)(n0 + r) * CH + c * 8);
                }
#pragma unroll
                for (int i = 0; i < 8; i++) {      // A = F transposed+masked
                    int e = tid + i * 128;
                    int b = e & 127, jg = e >> 7;
                    uint32_t w[4];
#pragma unroll
                    for (int p2 = 0; p2 < 4; p2++) {
                        int ja = jg * 8 + p2 * 2;
                        float v0 = (ja     <= u) ? f[(size_t)(t - ja) * BT + b] : 0.f;
                        float v1 = (ja + 1 <= u) ? f[(size_t)(t - ja - 1) * BT + b] : 0.f;
                        w[p2] = f2h2(v0, v1);
                    }
                    *(uint4*)(smem + s * STG_BYTES + sw_h(b, jg)) =
                        make_uint4(w[0], w[1], w[2], w[3]);
                }
            }
        }
        CP_COMMIT();
    };

    prefetch(0);
    prefetch(1);
    for (int it = 0; it < nT; ++it) {
        CP_WAIT1();
        __syncthreads();

        int s = it - (it / 3) * 3;
        uint32_t Au = s0 + (uint32_t)(s * STG_BYTES);
        uint32_t Bu = Au + 16384;
#pragma unroll
        for (int kt = 0; kt < 4; kt++) {
            uint32_t a[4][4], b[4][4];
#pragma unroll
            for (int mi = 0; mi < 4; mi++) {
                int r = wm * 64 + mi * 16 + a_r16;
                int c = kt * 2 + a_kc;
                ldsm4(Au + sw_h(r, c), a[mi][0], a[mi][1], a[mi][2], a[mi][3]);
            }
#pragma unroll
            for (int nbp = 0; nbp < 4; nbp++) {
                int r = wn * 64 + nbp * 16 + b_rb;
                int c = kt * 2 + b_kc;
                ldsm4(Bu + sw_h(r, c), b[nbp][0], b[nbp][1], b[nbp][2], b[nbp][3]);
            }
#pragma unroll
            for (int mi = 0; mi < 4; mi++)
#pragma unroll
                for (int n8 = 0; n8 < 8; n8++)
                    mma_f16(acc[mi][n8], a[mi][0], a[mi][1], a[mi][2], a[mi][3],
                            b[n8 >> 1][(n8 & 1) * 2], b[n8 >> 1][(n8 & 1) * 2 + 1]);
        }
        prefetch(it + 2);
    }

    float* __restrict__ o = out + (size_t)t * BT * NST + n0;
    const int er = wm * 64 + (lane >> 2);
    const int ec0 = wn * 64 + (lane & 3) * 2;
#pragma unroll
    for (int mi = 0; mi < 4; mi++) {
        int r0 = er + mi * 16;
#pragma unroll
        for (int n8 = 0; n8 < 8; n8++) {
            int c = ec0 + n8 * 8;
            *(float2*)&o[(size_t)r0 * NST + c] =
                make_float2(acc[mi][n8][0], acc[mi][n8][1]);
            *(float2*)&o[(size_t)(r0 + 8) * NST + c] =
                make_float2(acc[mi][n8][2], acc[mi][n8][3]);
        }
    }
}

// ---------------------------------------------------------------------------
extern "C" void kernel_launch(void* const* d_in, const int* in_sizes, int n_in,
                              void* d_out, int out_size) {
    const float* f = nullptr;
    const float* A = nullptr;
    const float* Bv = nullptr;
    for (int i = 0; i < n_in; i++) {
        if (in_sizes[i] == LSEQ * BT) f = (const float*)d_in[i];
        else if (in_sizes[i] == NST * NST) A = (const float*)d_in[i];
        else if (in_sizes[i] == NST) Bv = (const float*)d_in[i];
    }
    float* out = (float*)d_out;

    cudaFuncSetAttribute(k_main_mma, cudaFuncAttributeMaxDynamicSharedMemorySize,
                         SMEM_MAIN);
    cudaFuncSetAttribute(k_h1_mma, cudaFuncAttributeMaxDynamicSharedMemorySize,
                         49152);

    k_init<<<256, 256>>>(A, Bv);
    k_powers<<<48 * 32, 128>>>();
    k_kern<<<31, 256>>>(Bv);
    k_w2<<<dim3(2, NSUB), 256>>>(f);
    k_wg<<<dim3(2, NG), 256>>>();
    k_h1_mma<<<NPAIR, 256, 49152>>>();
    k_h2<<<(NG * BT * NST + 255) / 256, 256>>>();
    k_hsub<<<dim3(2, NG), 256>>>(1);
    k_hsub<<<dim3(2, NG), 256>>>(2);
    k_hsub<<<dim3(2, NG), 256>>>(3);
    k_main_mma<<<dim3(2, LSEQ), 128, SMEM_MAIN>>>(f, out);
    (void)out_size;
}